// round 1
// baseline (speedup 1.0000x reference)
#include <cuda_runtime.h>
#include <math.h>

// Problem constants
#define Nn    50000
#define Ee    800000
#define FEAT  512
#define HEADS 8
#define HID   64
#define C1    512    // HEADS*HID
#define NC    64     // NCLASS
#define ALPHA 0.2f

// ---------------- scratch (device globals; no allocation allowed) ----------
__device__ float g_Wh [(size_t)Nn * C1];   // layer1 Wh (concat heads)
__device__ float g_h1 [(size_t)Nn * C1];   // layer1 output (after ELU)
__device__ float g_Wh2[(size_t)Nn * NC];   // layer2 Wh
__device__ float g_fd1[Nn * HEADS];
__device__ float g_fs1[Nn * HEADS];
__device__ float g_fd2[Nn];
__device__ float g_fs2[Nn];
__device__ float g_lg1[(size_t)Ee * HEADS]; // logits -> att (in place)
__device__ float g_lg2[Ee];
__device__ float g_mx1[Nn * HEADS];
__device__ float g_iv1[Nn * HEADS];
__device__ float g_mx2[Nn];
__device__ float g_iv2[Nn];
__device__ int   g_cnt[Nn];
__device__ int   g_off[Nn + 1];
__device__ int   g_cur[Nn];
__device__ int   g_eidx[Ee];

// ---------------- CSR build ------------------------------------------------
__global__ void k_zero_cnt() {
    int i = blockIdx.x * blockDim.x + threadIdx.x;
    if (i < Nn) g_cnt[i] = 0;
}

__global__ void k_hist(const int* __restrict__ row) {
    int e = blockIdx.x * blockDim.x + threadIdx.x;
    if (e < Ee) atomicAdd(&g_cnt[row[e]], 1);
}

// single-block exclusive scan over g_cnt -> g_off (and g_cur copy)
__global__ void k_scan() {
    __shared__ int sh[2][1024];
    __shared__ int s_base;
    int t = threadIdx.x;
    if (t == 0) s_base = 0;
    __syncthreads();
    for (int start = 0; start < Nn; start += 1024) {
        int i = start + t;
        int v = (i < Nn) ? g_cnt[i] : 0;
        int orig = v;
        int pi = 0;
        sh[0][t] = v;
        __syncthreads();
        for (int s = 1; s < 1024; s <<= 1) {
            int w = sh[pi][t];
            if (t >= s) w += sh[pi][t - s];
            sh[pi ^ 1][t] = w;
            pi ^= 1;
            __syncthreads();
        }
        int incl = sh[pi][t];
        int base = s_base;
        if (i < Nn) {
            int ex = base + incl - orig;
            g_off[i] = ex;
            g_cur[i] = ex;
        }
        __syncthreads();
        if (t == 1023) s_base = base + incl;
        __syncthreads();
    }
    if (t == 0) g_off[Nn] = s_base;
}

__global__ void k_scatter(const int* __restrict__ row) {
    int e = blockIdx.x * blockDim.x + threadIdx.x;
    if (e < Ee) {
        int p = atomicAdd(&g_cur[row[e]], 1);
        g_eidx[p] = e;
    }
}

// ---------------- GEMM: C[M,Ncols] = A[M,512] @ B', fp32 -------------------
// B' element (k, n0+cc) = B[(n0>>6)*(512*64) + k*64 + cc]
//   layer1: B = W [8,512,64]  -> concatenated-head weight
//   layer2: B = W_out [512,64], n0 = 0
#define BM 128
#define BN 64
#define BK 16

__device__ __forceinline__ void gemm_core(const float* __restrict__ A,
                                          const float* __restrict__ B,
                                          float* __restrict__ C,
                                          int M, int Ncols) {
    __shared__ float As[BK][BM + 4];
    __shared__ float Bs[BK][BN];
    int t  = threadIdx.x;
    int m0 = blockIdx.x * BM;
    int n0 = blockIdx.y * BN;
    const float* bbase = B + (size_t)(n0 >> 6) * (512 * 64);
    int tx = t & 15;   // 0..15 -> 4 cols each
    int ty = t >> 4;   // 0..15 -> 8 rows each

    float acc[8][4];
#pragma unroll
    for (int r = 0; r < 8; r++)
#pragma unroll
        for (int c = 0; c < 4; c++) acc[r][c] = 0.f;

    for (int k0 = 0; k0 < 512; k0 += BK) {
        // load A tile (128 x 16)
#pragma unroll
        for (int i = 0; i < 2; i++) {
            int idx = t + i * 256;      // 0..511 float4 slots
            int rrow = idx >> 2;        // 0..127
            int kk4 = (idx & 3) << 2;   // 0,4,8,12
            float4 v = make_float4(0.f, 0.f, 0.f, 0.f);
            int gr = m0 + rrow;
            if (gr < M) v = *(const float4*)(A + (size_t)gr * 512 + k0 + kk4);
            As[kk4 + 0][rrow] = v.x;
            As[kk4 + 1][rrow] = v.y;
            As[kk4 + 2][rrow] = v.z;
            As[kk4 + 3][rrow] = v.w;
        }
        // load B tile (16 x 64)
        {
            int kk  = t >> 4;
            int cc4 = (t & 15) << 2;
            float4 v = *(const float4*)(bbase + (size_t)(k0 + kk) * 64 + cc4);
            *(float4*)&Bs[kk][cc4] = v;
        }
        __syncthreads();
#pragma unroll
        for (int kk = 0; kk < BK; kk++) {
            float av[8], bv[4];
#pragma unroll
            for (int r = 0; r < 8; r++) av[r] = As[kk][ty * 8 + r];
#pragma unroll
            for (int c = 0; c < 4; c++) bv[c] = Bs[kk][tx * 4 + c];
#pragma unroll
            for (int r = 0; r < 8; r++)
#pragma unroll
                for (int c = 0; c < 4; c++) acc[r][c] = fmaf(av[r], bv[c], acc[r][c]);
        }
        __syncthreads();
    }
#pragma unroll
    for (int r = 0; r < 8; r++) {
        int gr = m0 + ty * 8 + r;
        if (gr < M) {
            float4 v = make_float4(acc[r][0], acc[r][1], acc[r][2], acc[r][3]);
            *(float4*)(C + (size_t)gr * Ncols + n0 + tx * 4) = v;
        }
    }
}

__global__ void __launch_bounds__(256) k_gemm1(const float* __restrict__ x,
                                               const float* __restrict__ W) {
    gemm_core(x, W, g_Wh, Nn, C1);
}
__global__ void __launch_bounds__(256) k_gemm2(const float* __restrict__ W_out) {
    gemm_core(g_h1, W_out, g_Wh2, Nn, NC);
}

// ---------------- layer1: f_dst/f_src per node ------------------------------
__global__ void k_f1(const float* __restrict__ a) {
    int i = blockIdx.x;
    int t = threadIdx.x;  // 256
    __shared__ float sd[512], ss[512];
    const float* whr = g_Wh + (size_t)i * 512;
    float v0 = whr[t], v1 = whr[t + 256];
    int h0 = t >> 6, j0 = t & 63;
    int idx1 = t + 256;
    int h1 = idx1 >> 6, j1 = idx1 & 63;
    sd[t]      = v0 * a[h0 * 128 + j0];
    ss[t]      = v0 * a[h0 * 128 + 64 + j0];
    sd[idx1]   = v1 * a[h1 * 128 + j1];
    ss[idx1]   = v1 * a[h1 * 128 + 64 + j1];
    __syncthreads();
    if (t < 16) {
        int h = t & 7;
        const float* buf = (t < 8) ? sd : ss;
        float s = 0.f;
#pragma unroll
        for (int j = 0; j < 64; j++) s += buf[h * 64 + j];
        if (t < 8) g_fd1[i * 8 + h] = s;
        else       g_fs1[i * 8 + h] = s;
    }
}

// ---------------- layer1: edge logits (leaky relu) --------------------------
__global__ void k_logits1(const int* __restrict__ row, const int* __restrict__ col) {
    int e = blockIdx.x * blockDim.x + threadIdx.x;
    if (e >= Ee) return;
    int r = row[e], c = col[e];
    float4 d0 = *(const float4*)(g_fd1 + r * 8);
    float4 d1 = *(const float4*)(g_fd1 + r * 8 + 4);
    float4 s0 = *(const float4*)(g_fs1 + c * 8);
    float4 s1 = *(const float4*)(g_fs1 + c * 8 + 4);
    float v[8] = {d0.x + s0.x, d0.y + s0.y, d0.z + s0.z, d0.w + s0.w,
                  d1.x + s1.x, d1.y + s1.y, d1.z + s1.z, d1.w + s1.w};
#pragma unroll
    for (int h = 0; h < 8; h++) v[h] = v[h] > 0.f ? v[h] : ALPHA * v[h];
    *(float4*)(g_lg1 + (size_t)e * 8)     = make_float4(v[0], v[1], v[2], v[3]);
    *(float4*)(g_lg1 + (size_t)e * 8 + 4) = make_float4(v[4], v[5], v[6], v[7]);
}

// ---------------- layer1: per (node,head) max + sumexp -----------------------
__global__ void k_maxsum1() {
    int t = blockIdx.x * blockDim.x + threadIdx.x;
    if (t >= Nn * 8) return;
    int i = t >> 3, h = t & 7;
    int o = g_off[i], oe = g_off[i + 1];
    float mx = -3.4e38f;
    for (int p = o; p < oe; p++) {
        int eid = g_eidx[p];
        float v = g_lg1[(size_t)eid * 8 + h];
        mx = fmaxf(mx, v);
    }
    float s = 0.f;
    for (int p = o; p < oe; p++) {
        int eid = g_eidx[p];
        s += __expf(g_lg1[(size_t)eid * 8 + h] - mx);
    }
    float iv = (oe > o) ? 1.f / fmaxf(s, 1e-16f) : 0.f;
    if (oe == o) mx = 0.f;
    g_mx1[t] = mx;
    g_iv1[t] = iv;
}

// ---------------- layer1: normalize logits -> att (in place) ----------------
__global__ void k_att1(const int* __restrict__ row) {
    long long t = (long long)blockIdx.x * blockDim.x + threadIdx.x;
    if (t >= (long long)Ee * 8) return;
    int e = (int)(t >> 3), h = (int)(t & 7);
    int r = row[e];
    g_lg1[t] = __expf(g_lg1[t] - g_mx1[r * 8 + h]) * g_iv1[r * 8 + h];
}

// ---------------- layer1: aggregation + ELU (one CTA per dst node) ----------
__global__ void __launch_bounds__(256) k_agg1(const int* __restrict__ col) {
    int i = blockIdx.x;
    int t = threadIdx.x;  // 256: dims t and t+256
    int o = g_off[i], oe = g_off[i + 1];
    int ha = t >> 6;        // head for dim t     (0..3)
    int hb = ha + 4;        // head for dim t+256 (4..7)
    float acc0 = 0.f, acc1 = 0.f;
    for (int p = o; p < oe; p++) {
        int eid = g_eidx[p];
        int c   = col[eid];
        float w0 = g_lg1[(size_t)eid * 8 + ha];
        float w1 = g_lg1[(size_t)eid * 8 + hb];
        const float* whc = g_Wh + (size_t)c * 512;
        acc0 = fmaf(w0, whc[t], acc0);
        acc1 = fmaf(w1, whc[t + 256], acc1);
    }
    float* dst = g_h1 + (size_t)i * 512;
    dst[t]       = acc0 > 0.f ? acc0 : (__expf(acc0) - 1.f);
    dst[t + 256] = acc1 > 0.f ? acc1 : (__expf(acc1) - 1.f);
}

// ---------------- layer2: f_dst/f_src (warp per node) ------------------------
__global__ void k_f2(const float* __restrict__ a_out) {
    int gt = blockIdx.x * blockDim.x + threadIdx.x;
    int w  = gt >> 5;
    int ln = gt & 31;
    if (w >= Nn) return;
    float v0 = g_Wh2[(size_t)w * 64 + ln];
    float v1 = g_Wh2[(size_t)w * 64 + 32 + ln];
    float pd = v0 * a_out[ln]      + v1 * a_out[ln + 32];
    float ps = v0 * a_out[64 + ln] + v1 * a_out[96 + ln];
#pragma unroll
    for (int s = 16; s > 0; s >>= 1) {
        pd += __shfl_down_sync(0xffffffffu, pd, s);
        ps += __shfl_down_sync(0xffffffffu, ps, s);
    }
    if (ln == 0) { g_fd2[w] = pd; g_fs2[w] = ps; }
}

__global__ void k_logits2(const int* __restrict__ row, const int* __restrict__ col) {
    int e = blockIdx.x * blockDim.x + threadIdx.x;
    if (e >= Ee) return;
    float v = g_fd2[row[e]] + g_fs2[col[e]];
    g_lg2[e] = v > 0.f ? v : ALPHA * v;
}

__global__ void k_maxsum2() {
    int i = blockIdx.x * blockDim.x + threadIdx.x;
    if (i >= Nn) return;
    int o = g_off[i], oe = g_off[i + 1];
    float mx = -3.4e38f;
    for (int p = o; p < oe; p++) mx = fmaxf(mx, g_lg2[g_eidx[p]]);
    float s = 0.f;
    for (int p = o; p < oe; p++) s += __expf(g_lg2[g_eidx[p]] - mx);
    float iv = (oe > o) ? 1.f / fmaxf(s, 1e-16f) : 0.f;
    if (oe == o) mx = 0.f;
    g_mx2[i] = mx;
    g_iv2[i] = iv;
}

__global__ void k_att2(const int* __restrict__ row) {
    int e = blockIdx.x * blockDim.x + threadIdx.x;
    if (e >= Ee) return;
    int r = row[e];
    g_lg2[e] = __expf(g_lg2[e] - g_mx2[r]) * g_iv2[r];
}

__global__ void __launch_bounds__(64) k_agg2(const int* __restrict__ col,
                                             float* __restrict__ out) {
    int i = blockIdx.x;
    int t = threadIdx.x;  // 64 dims
    int o = g_off[i], oe = g_off[i + 1];
    float acc = 0.f;
    for (int p = o; p < oe; p++) {
        int eid = g_eidx[p];
        int c   = col[eid];
        acc = fmaf(g_lg2[eid], g_Wh2[(size_t)c * 64 + t], acc);
    }
    out[(size_t)i * 64 + t] = acc;   // concat=False: no activation
}

// ---------------- launch -----------------------------------------------------
extern "C" void kernel_launch(void* const* d_in, const int* in_sizes, int n_in,
                              void* d_out, int out_size) {
    const float* x     = (const float*)d_in[0];
    const int*   row   = (const int*)  d_in[1];
    const int*   col   = (const int*)  d_in[2];
    const float* W     = (const float*)d_in[3];
    const float* a     = (const float*)d_in[4];
    const float* W_out = (const float*)d_in[5];
    const float* a_out = (const float*)d_in[6];
    float* out = (float*)d_out;

    const int EB = (Ee + 255) / 256;

    // CSR build (counting sort by destination node)
    k_zero_cnt<<<(Nn + 255) / 256, 256>>>();
    k_hist<<<EB, 256>>>(row);
    k_scan<<<1, 1024>>>();
    k_scatter<<<EB, 256>>>(row);

    // layer 1
    dim3 g1((Nn + BM - 1) / BM, C1 / BN);
    k_gemm1<<<g1, 256>>>(x, W);
    k_f1<<<Nn, 256>>>(a);
    k_logits1<<<EB, 256>>>(row, col);
    k_maxsum1<<<(Nn * 8 + 255) / 256, 256>>>();
    k_att1<<<(Ee * 8 + 255) / 256, 256>>>(row);
    k_agg1<<<Nn, 256>>>(col);

    // layer 2
    dim3 g2((Nn + BM - 1) / BM, NC / BN);
    k_gemm2<<<g2, 256>>>(W_out);
    k_f2<<<(Nn * 32 + 255) / 256, 256>>>(a_out);
    k_logits2<<<EB, 256>>>(row, col);
    k_maxsum2<<<(Nn + 255) / 256, 256>>>();
    k_att2<<<EB, 256>>>(row);
    k_agg2<<<Nn, 64>>>(col, out);
}

// round 4
// speedup vs baseline: 1.3458x; 1.3458x over previous
#include <cuda_runtime.h>
#include <cuda_bf16.h>
#include <stdint.h>
#include <math.h>

// Problem constants
#define Nn    50000
#define Mpad  50048           // padded rows for 128-tiles
#define Ee    800000
#define FEAT  512
#define HEADS 8
#define HID   64
#define C1    512    // HEADS*HID
#define NC    64     // NCLASS
#define ALPHA 0.2f

// ---------------- scratch (device globals; no allocation allowed) ----------
__device__ float g_Wh [(size_t)Nn * C1];   // layer1 Wh (concat heads)
__device__ float g_h1 [(size_t)Nn * C1];   // layer1 output (after ELU)
__device__ float g_Wh2[(size_t)Nn * NC];   // layer2 Wh
__device__ float g_fd1[Nn * HEADS];
__device__ float g_fs1[Nn * HEADS];
__device__ float g_fd2[Nn];
__device__ float g_fs2[Nn];
__device__ float g_lg1[(size_t)Ee * HEADS]; // logits -> att (in place)
__device__ float g_lg2[Ee];
__device__ float g_mx1[Nn * HEADS];
__device__ float g_iv1[Nn * HEADS];
__device__ float g_mx2[Nn];
__device__ float g_iv2[Nn];
__device__ int   g_cnt[Nn];
__device__ int   g_off[Nn + 1];
__device__ int   g_cur[Nn];
__device__ int   g_eidx[Ee];

// bf16 hi/lo operands for the tensor-core GEMM1
__device__ __align__(256) __nv_bfloat16 g_xhi[(size_t)Mpad * 512];
__device__ __align__(256) __nv_bfloat16 g_xlo[(size_t)Mpad * 512];
__device__ __align__(256) __nv_bfloat16 g_bhi[512 * 512];   // Bt[n][k]
__device__ __align__(256) __nv_bfloat16 g_blo[512 * 512];

// ---------------- small PTX helpers ----------------------------------------
__device__ __forceinline__ uint32_t smem_u32(const void* p) {
    uint32_t a;
    asm("{ .reg .u64 t; cvta.to.shared.u64 t, %1; cvt.u32.u64 %0, t; }" : "=r"(a) : "l"(p));
    return a;
}
__device__ __forceinline__ void cpa16(uint32_t dst, const void* src) {
    asm volatile("cp.async.cg.shared.global [%0], [%1], 16;" :: "r"(dst), "l"(src));
}
__device__ __forceinline__ void cpa_commit() {
    asm volatile("cp.async.commit_group;" ::: "memory");
}
template <int N> __device__ __forceinline__ void cpa_wait() {
    asm volatile("cp.async.wait_group %0;" :: "n"(N) : "memory");
}
__device__ __forceinline__ void ldm4(uint32_t* r, uint32_t addr) {
    asm volatile("ldmatrix.sync.aligned.m8n8.x4.shared.b16 {%0,%1,%2,%3}, [%4];"
                 : "=r"(r[0]), "=r"(r[1]), "=r"(r[2]), "=r"(r[3]) : "r"(addr));
}
__device__ __forceinline__ void mma16816(float* c, const uint32_t* a,
                                         uint32_t b0, uint32_t b1) {
    asm volatile(
        "mma.sync.aligned.m16n8k16.row.col.f32.bf16.bf16.f32 "
        "{%0,%1,%2,%3}, {%4,%5,%6,%7}, {%8,%9}, {%0,%1,%2,%3};"
        : "+f"(c[0]), "+f"(c[1]), "+f"(c[2]), "+f"(c[3])
        : "r"(a[0]), "r"(a[1]), "r"(a[2]), "r"(a[3]), "r"(b0), "r"(b1));
}

// ---------------- bf16 hi/lo conversion kernels ------------------------------
__global__ void k_cvt_x(const float* __restrict__ x) {
    long long i4 = (long long)blockIdx.x * blockDim.x + threadIdx.x; // float4 idx
    if (i4 >= (long long)Mpad * 128) return;
    long long row = i4 >> 7;
    float4 v = make_float4(0.f, 0.f, 0.f, 0.f);
    if (row < Nn) v = ((const float4*)x)[i4];
    __nv_bfloat16 h0 = __float2bfloat16_rn(v.x);
    __nv_bfloat16 h1 = __float2bfloat16_rn(v.y);
    __nv_bfloat16 h2 = __float2bfloat16_rn(v.z);
    __nv_bfloat16 h3 = __float2bfloat16_rn(v.w);
    __nv_bfloat16 l0 = __float2bfloat16_rn(v.x - __bfloat162float(h0));
    __nv_bfloat16 l1 = __float2bfloat16_rn(v.y - __bfloat162float(h1));
    __nv_bfloat16 l2 = __float2bfloat16_rn(v.z - __bfloat162float(h2));
    __nv_bfloat16 l3 = __float2bfloat16_rn(v.w - __bfloat162float(h3));
    __nv_bfloat16* ph = g_xhi + i4 * 4;
    __nv_bfloat16* pl = g_xlo + i4 * 4;
    ph[0] = h0; ph[1] = h1; ph[2] = h2; ph[3] = h3;
    pl[0] = l0; pl[1] = l1; pl[2] = l2; pl[3] = l3;
}

__global__ void k_cvt_w(const float* __restrict__ W) {
    int idx = blockIdx.x * blockDim.x + threadIdx.x;  // n*512 + k
    if (idx >= 512 * 512) return;
    int n = idx >> 9, k = idx & 511;
    float v = W[(size_t)(n >> 6) * (512 * 64) + (size_t)k * 64 + (n & 63)];
    __nv_bfloat16 h = __float2bfloat16_rn(v);
    __nv_bfloat16 l = __float2bfloat16_rn(v - __bfloat162float(h));
    g_bhi[idx] = h;
    g_blo[idx] = l;
}

// ---------------- HMMA GEMM1: g_Wh[M,512] = x @ Wcat ------------------------
// CTA tile 128x128, 8 warps (warp tile 32x64), K chunks of 32, double buffer.
// smem stage: Ah[128][40], Al, Bh, Bl (bf16, 80B padded rows -> conflict-free
// ldmatrix: row offsets mod 128B all distinct).
#define A_HI 0
#define A_LO 10240
#define B_HI 20480
#define B_LO 30720
#define STAGE 40960
#define SMEM_GEMM_TOTAL (2 * STAGE)

__device__ __forceinline__ void load_stage(uint32_t s, int t, int m0, int n0, int kc) {
    int k0 = kc * 32;
#pragma unroll
    for (int i = 0; i < 2; i++) {
        int idx = t + i * 256;          // 0..511
        int r = idx >> 2;               // row 0..127
        int c = idx & 3;                // 16B chunk
        uint32_t d = s + (uint32_t)(r * 80 + c * 16);
        size_t sa = (size_t)(m0 + r) * 512 + k0 + c * 8;
        size_t sbg = (size_t)(n0 + r) * 512 + k0 + c * 8;
        cpa16(d + A_HI, g_xhi + sa);
        cpa16(d + A_LO, g_xlo + sa);
        cpa16(d + B_HI, g_bhi + sbg);
        cpa16(d + B_LO, g_blo + sbg);
    }
    cpa_commit();
}

__global__ void __launch_bounds__(256) k_gemm1_mma() {
    extern __shared__ char smem[];
    uint32_t sb = smem_u32(smem);
    const int t = threadIdx.x;
    const int lane = t & 31, w = t >> 5;
    const int wm = w & 3, wn = w >> 2;          // warp grid 4(m) x 2(n)
    const int m0 = blockIdx.x * 128, n0 = blockIdx.y * 128;

    float acc[2][8][4];
#pragma unroll
    for (int mf = 0; mf < 2; mf++)
#pragma unroll
        for (int nf = 0; nf < 8; nf++)
#pragma unroll
            for (int q = 0; q < 4; q++) acc[mf][nf][q] = 0.f;

    load_stage(sb, t, m0, n0, 0);

    // ldmatrix lane-address components (constant across k-chunks)
    const int a_row = wm * 32 + (lane & 15);         // + mf*16
    const int a_colb = (lane >> 4) * 8;              // + ks*16
    const int b_row = wn * 64 + ((lane >> 4) & 1) * 8 + (lane & 7);  // + nb*16
    const int b_colb = ((lane >> 3) & 1) * 8;        // + ks*16

    for (int kc = 0; kc < 16; kc++) {
        uint32_t s = sb + (uint32_t)(kc & 1) * STAGE;
        if (kc + 1 < 16) load_stage(sb + (uint32_t)((kc + 1) & 1) * STAGE, t, m0, n0, kc + 1);
        if (kc + 1 < 16) { cpa_wait<1>(); } else { cpa_wait<0>(); }
        __syncthreads();

#pragma unroll
        for (int ks = 0; ks < 2; ks++) {
            uint32_t ah[2][4], al[2][4];
#pragma unroll
            for (int mf = 0; mf < 2; mf++) {
                uint32_t ad = s + (uint32_t)((a_row + mf * 16) * 80 + (ks * 16 + a_colb) * 2);
                ldm4(ah[mf], ad + A_HI);
                ldm4(al[mf], ad + A_LO);
            }
            uint32_t bh[4][4], bl[4][4];
#pragma unroll
            for (int nb = 0; nb < 4; nb++) {
                uint32_t bd = s + (uint32_t)((b_row + nb * 16) * 80 + (ks * 16 + b_colb) * 2);
                ldm4(bh[nb], bd + B_HI);
                ldm4(bl[nb], bd + B_LO);
            }
#pragma unroll
            for (int mf = 0; mf < 2; mf++)
#pragma unroll
                for (int nb = 0; nb < 4; nb++)
#pragma unroll
                    for (int half = 0; half < 2; half++) {
                        float* c = acc[mf][nb * 2 + half];
                        mma16816(c, ah[mf], bh[nb][half * 2], bh[nb][half * 2 + 1]);
                        mma16816(c, ah[mf], bl[nb][half * 2], bl[nb][half * 2 + 1]);
                        mma16816(c, al[mf], bh[nb][half * 2], bh[nb][half * 2 + 1]);
                    }
        }
        __syncthreads();
    }

    // epilogue: C fragment -> g_Wh
#pragma unroll
    for (int mf = 0; mf < 2; mf++) {
        int r0 = m0 + wm * 32 + mf * 16 + (lane >> 2);
#pragma unroll
        for (int nf = 0; nf < 8; nf++) {
            int cc = n0 + wn * 64 + nf * 8 + (lane & 3) * 2;
            float* c = acc[mf][nf];
            if (r0 < Nn)
                *(float2*)(g_Wh + (size_t)r0 * 512 + cc) = make_float2(c[0], c[1]);
            if (r0 + 8 < Nn)
                *(float2*)(g_Wh + (size_t)(r0 + 8) * 512 + cc) = make_float2(c[2], c[3]);
        }
    }
}

// ---------------- CSR build ------------------------------------------------
__global__ void k_zero_cnt() {
    int i = blockIdx.x * blockDim.x + threadIdx.x;
    if (i < Nn) g_cnt[i] = 0;
}

__global__ void k_hist(const int* __restrict__ row) {
    int e = blockIdx.x * blockDim.x + threadIdx.x;
    if (e < Ee) atomicAdd(&g_cnt[row[e]], 1);
}

__global__ void k_scan() {
    __shared__ int sh[2][1024];
    __shared__ int s_base;
    int t = threadIdx.x;
    if (t == 0) s_base = 0;
    __syncthreads();
    for (int start = 0; start < Nn; start += 1024) {
        int i = start + t;
        int v = (i < Nn) ? g_cnt[i] : 0;
        int orig = v;
        int pi = 0;
        sh[0][t] = v;
        __syncthreads();
        for (int s = 1; s < 1024; s <<= 1) {
            int w = sh[pi][t];
            if (t >= s) w += sh[pi][t - s];
            sh[pi ^ 1][t] = w;
            pi ^= 1;
            __syncthreads();
        }
        int incl = sh[pi][t];
        int base = s_base;
        if (i < Nn) {
            int ex = base + incl - orig;
            g_off[i] = ex;
            g_cur[i] = ex;
        }
        __syncthreads();
        if (t == 1023) s_base = base + incl;
        __syncthreads();
    }
    if (t == 0) g_off[Nn] = s_base;
}

__global__ void k_scatter(const int* __restrict__ row) {
    int e = blockIdx.x * blockDim.x + threadIdx.x;
    if (e < Ee) {
        int p = atomicAdd(&g_cur[row[e]], 1);
        g_eidx[p] = e;
    }
}

// ---------------- SIMT GEMM (layer 2 only) ----------------------------------
#define BM 128
#define BN 64
#define BK 16

__device__ __forceinline__ void gemm_core(const float* __restrict__ A,
                                          const float* __restrict__ B,
                                          float* __restrict__ C,
                                          int M, int Ncols) {
    __shared__ float As[BK][BM + 4];
    __shared__ float Bs[BK][BN];
    int t  = threadIdx.x;
    int m0 = blockIdx.x * BM;
    int n0 = blockIdx.y * BN;
    const float* bbase = B + (size_t)(n0 >> 6) * (512 * 64);
    int tx = t & 15;
    int ty = t >> 4;

    float acc[8][4];
#pragma unroll
    for (int r = 0; r < 8; r++)
#pragma unroll
        for (int c = 0; c < 4; c++) acc[r][c] = 0.f;

    for (int k0 = 0; k0 < 512; k0 += BK) {
#pragma unroll
        for (int i = 0; i < 2; i++) {
            int idx = t + i * 256;
            int rrow = idx >> 2;
            int kk4 = (idx & 3) << 2;
            float4 v = make_float4(0.f, 0.f, 0.f, 0.f);
            int gr = m0 + rrow;
            if (gr < M) v = *(const float4*)(A + (size_t)gr * 512 + k0 + kk4);
            As[kk4 + 0][rrow] = v.x;
            As[kk4 + 1][rrow] = v.y;
            As[kk4 + 2][rrow] = v.z;
            As[kk4 + 3][rrow] = v.w;
        }
        {
            int kk  = t >> 4;
            int cc4 = (t & 15) << 2;
            float4 v = *(const float4*)(bbase + (size_t)(k0 + kk) * 64 + cc4);
            *(float4*)&Bs[kk][cc4] = v;
        }
        __syncthreads();
#pragma unroll
        for (int kk = 0; kk < BK; kk++) {
            float av[8], bv[4];
#pragma unroll
            for (int r = 0; r < 8; r++) av[r] = As[kk][ty * 8 + r];
#pragma unroll
            for (int c = 0; c < 4; c++) bv[c] = Bs[kk][tx * 4 + c];
#pragma unroll
            for (int r = 0; r < 8; r++)
#pragma unroll
                for (int c = 0; c < 4; c++) acc[r][c] = fmaf(av[r], bv[c], acc[r][c]);
        }
        __syncthreads();
    }
#pragma unroll
    for (int r = 0; r < 8; r++) {
        int gr = m0 + ty * 8 + r;
        if (gr < M) {
            float4 v = make_float4(acc[r][0], acc[r][1], acc[r][2], acc[r][3]);
            *(float4*)(C + (size_t)gr * Ncols + n0 + tx * 4) = v;
        }
    }
}

__global__ void __launch_bounds__(256) k_gemm2(const float* __restrict__ W_out) {
    gemm_core(g_h1, W_out, g_Wh2, Nn, NC);
}

// ---------------- layer1: f_dst/f_src per node ------------------------------
__global__ void k_f1(const float* __restrict__ a) {
    int i = blockIdx.x;
    int t = threadIdx.x;  // 256
    __shared__ float sd[512], ss[512];
    const float* whr = g_Wh + (size_t)i * 512;
    float v0 = whr[t], v1 = whr[t + 256];
    int h0 = t >> 6, j0 = t & 63;
    int idx1 = t + 256;
    int h1 = idx1 >> 6, j1 = idx1 & 63;
    sd[t]      = v0 * a[h0 * 128 + j0];
    ss[t]      = v0 * a[h0 * 128 + 64 + j0];
    sd[idx1]   = v1 * a[h1 * 128 + j1];
    ss[idx1]   = v1 * a[h1 * 128 + 64 + j1];
    __syncthreads();
    if (t < 16) {
        int h = t & 7;
        const float* buf = (t < 8) ? sd : ss;
        float s = 0.f;
#pragma unroll
        for (int j = 0; j < 64; j++) s += buf[h * 64 + j];
        if (t < 8) g_fd1[i * 8 + h] = s;
        else       g_fs1[i * 8 + h] = s;
    }
}

// ---------------- layer1: edge logits (leaky relu) --------------------------
__global__ void k_logits1(const int* __restrict__ row, const int* __restrict__ col) {
    int e = blockIdx.x * blockDim.x + threadIdx.x;
    if (e >= Ee) return;
    int r = row[e], c = col[e];
    float4 d0 = *(const float4*)(g_fd1 + r * 8);
    float4 d1 = *(const float4*)(g_fd1 + r * 8 + 4);
    float4 s0 = *(const float4*)(g_fs1 + c * 8);
    float4 s1 = *(const float4*)(g_fs1 + c * 8 + 4);
    float v[8] = {d0.x + s0.x, d0.y + s0.y, d0.z + s0.z, d0.w + s0.w,
                  d1.x + s1.x, d1.y + s1.y, d1.z + s1.z, d1.w + s1.w};
#pragma unroll
    for (int h = 0; h < 8; h++) v[h] = v[h] > 0.f ? v[h] : ALPHA * v[h];
    *(float4*)(g_lg1 + (size_t)e * 8)     = make_float4(v[0], v[1], v[2], v[3]);
    *(float4*)(g_lg1 + (size_t)e * 8 + 4) = make_float4(v[4], v[5], v[6], v[7]);
}

// ---------------- layer1: per (node,head) max + sumexp -----------------------
__global__ void k_maxsum1() {
    int t = blockIdx.x * blockDim.x + threadIdx.x;
    if (t >= Nn * 8) return;
    int i = t >> 3, h = t & 7;
    int o = g_off[i], oe = g_off[i + 1];
    float mx = -3.4e38f;
    for (int p = o; p < oe; p++) {
        int eid = g_eidx[p];
        float v = g_lg1[(size_t)eid * 8 + h];
        mx = fmaxf(mx, v);
    }
    float s = 0.f;
    for (int p = o; p < oe; p++) {
        int eid = g_eidx[p];
        s += __expf(g_lg1[(size_t)eid * 8 + h] - mx);
    }
    float iv = (oe > o) ? 1.f / fmaxf(s, 1e-16f) : 0.f;
    if (oe == o) mx = 0.f;
    g_mx1[t] = mx;
    g_iv1[t] = iv;
}

// ---------------- layer1: normalize logits -> att (in place) ----------------
__global__ void k_att1(const int* __restrict__ row) {
    long long t = (long long)blockIdx.x * blockDim.x + threadIdx.x;
    if (t >= (long long)Ee * 8) return;
    int e = (int)(t >> 3), h = (int)(t & 7);
    int r = row[e];
    g_lg1[t] = __expf(g_lg1[t] - g_mx1[r * 8 + h]) * g_iv1[r * 8 + h];
}

// ---------------- layer1: aggregation + ELU (one CTA per dst node) ----------
__global__ void __launch_bounds__(256) k_agg1(const int* __restrict__ col) {
    int i = blockIdx.x;
    int t = threadIdx.x;
    int o = g_off[i], oe = g_off[i + 1];
    int ha = t >> 6;
    int hb = ha + 4;
    float acc0 = 0.f, acc1 = 0.f;
    for (int p = o; p < oe; p++) {
        int eid = g_eidx[p];
        int c   = col[eid];
        float w0 = g_lg1[(size_t)eid * 8 + ha];
        float w1 = g_lg1[(size_t)eid * 8 + hb];
        const float* whc = g_Wh + (size_t)c * 512;
        acc0 = fmaf(w0, whc[t], acc0);
        acc1 = fmaf(w1, whc[t + 256], acc1);
    }
    float* dst = g_h1 + (size_t)i * 512;
    dst[t]       = acc0 > 0.f ? acc0 : (__expf(acc0) - 1.f);
    dst[t + 256] = acc1 > 0.f ? acc1 : (__expf(acc1) - 1.f);
}

// ---------------- layer2: f_dst/f_src (warp per node) ------------------------
__global__ void k_f2(const float* __restrict__ a_out) {
    int gt = blockIdx.x * blockDim.x + threadIdx.x;
    int w  = gt >> 5;
    int ln = gt & 31;
    if (w >= Nn) return;
    float v0 = g_Wh2[(size_t)w * 64 + ln];
    float v1 = g_Wh2[(size_t)w * 64 + 32 + ln];
    float pd = v0 * a_out[ln]      + v1 * a_out[ln + 32];
    float ps = v0 * a_out[64 + ln] + v1 * a_out[96 + ln];
#pragma unroll
    for (int s = 16; s > 0; s >>= 1) {
        pd += __shfl_down_sync(0xffffffffu, pd, s);
        ps += __shfl_down_sync(0xffffffffu, ps, s);
    }
    if (ln == 0) { g_fd2[w] = pd; g_fs2[w] = ps; }
}

__global__ void k_logits2(const int* __restrict__ row, const int* __restrict__ col) {
    int e = blockIdx.x * blockDim.x + threadIdx.x;
    if (e >= Ee) return;
    float v = g_fd2[row[e]] + g_fs2[col[e]];
    g_lg2[e] = v > 0.f ? v : ALPHA * v;
}

__global__ void k_maxsum2() {
    int i = blockIdx.x * blockDim.x + threadIdx.x;
    if (i >= Nn) return;
    int o = g_off[i], oe = g_off[i + 1];
    float mx = -3.4e38f;
    for (int p = o; p < oe; p++) mx = fmaxf(mx, g_lg2[g_eidx[p]]);
    float s = 0.f;
    for (int p = o; p < oe; p++) s += __expf(g_lg2[g_eidx[p]] - mx);
    float iv = (oe > o) ? 1.f / fmaxf(s, 1e-16f) : 0.f;
    if (oe == o) mx = 0.f;
    g_mx2[i] = mx;
    g_iv2[i] = iv;
}

__global__ void k_att2(const int* __restrict__ row) {
    int e = blockIdx.x * blockDim.x + threadIdx.x;
    if (e >= Ee) return;
    int r = row[e];
    g_lg2[e] = __expf(g_lg2[e] - g_mx2[r]) * g_iv2[r];
}

__global__ void __launch_bounds__(64) k_agg2(const int* __restrict__ col,
                                             float* __restrict__ out) {
    int i = blockIdx.x;
    int t = threadIdx.x;
    int o = g_off[i], oe = g_off[i + 1];
    float acc = 0.f;
    for (int p = o; p < oe; p++) {
        int eid = g_eidx[p];
        int c   = col[eid];
        acc = fmaf(g_lg2[eid], g_Wh2[(size_t)c * 64 + t], acc);
    }
    out[(size_t)i * 64 + t] = acc;
}

// ---------------- launch -----------------------------------------------------
extern "C" void kernel_launch(void* const* d_in, const int* in_sizes, int n_in,
                              void* d_out, int out_size) {
    const float* x     = (const float*)d_in[0];
    const int*   row   = (const int*)  d_in[1];
    const int*   col   = (const int*)  d_in[2];
    const float* W     = (const float*)d_in[3];
    const float* a     = (const float*)d_in[4];
    const float* W_out = (const float*)d_in[5];
    const float* a_out = (const float*)d_in[6];
    float* out = (float*)d_out;

    const int EB = (Ee + 255) / 256;

    cudaFuncSetAttribute(k_gemm1_mma, cudaFuncAttributeMaxDynamicSharedMemorySize,
                         SMEM_GEMM_TOTAL);

    // operand conversion for tensor-core GEMM1
    k_cvt_x<<<(int)(((long long)Mpad * 128 + 255) / 256), 256>>>(x);
    k_cvt_w<<<(512 * 512 + 255) / 256, 256>>>(W);

    // CSR build (counting sort by destination node)
    k_zero_cnt<<<(Nn + 255) / 256, 256>>>();
    k_hist<<<EB, 256>>>(row);
    k_scan<<<1, 1024>>>();
    k_scatter<<<EB, 256>>>(row);

    // layer 1
    k_gemm1_mma<<<dim3(Mpad / 128, 4), 256, SMEM_GEMM_TOTAL>>>();
    k_f1<<<Nn, 256>>>(a);
    k_logits1<<<EB, 256>>>(row, col);
    k_maxsum1<<<(Nn * 8 + 255) / 256, 256>>>();
    k_att1<<<(Ee * 8 + 255) / 256, 256>>>(row);
    k_agg1<<<Nn, 256>>>(col);

    // layer 2
    dim3 g2((Nn + BM - 1) / BM, NC / BN);
    k_gemm2<<<g2, 256>>>(W_out);
    k_f2<<<(Nn * 32 + 255) / 256, 256>>>(a_out);
    k_logits2<<<EB, 256>>>(row, col);
    k_maxsum2<<<(Nn + 255) / 256, 256>>>();
    k_att2<<<EB, 256>>>(row);
    k_agg2<<<Nn, 64>>>(col, out);
}

// round 5
// speedup vs baseline: 1.5610x; 1.1599x over previous
#include <cuda_runtime.h>
#include <cuda_bf16.h>
#include <stdint.h>
#include <math.h>

// Problem constants
#define Nn    50000
#define Mpad  50048           // padded rows for 128-tiles
#define Ee    800000
#define FEAT  512
#define HEADS 8
#define HID   64
#define C1    512    // HEADS*HID
#define NC    64     // NCLASS
#define ALPHA 0.2f

// ---------------- scratch (device globals; no allocation allowed) ----------
__device__ float g_Wh [(size_t)Nn * C1];   // layer1 Wh (concat heads)
__device__ float g_Wh2[(size_t)Nn * NC];   // layer2 Wh
__device__ float g_fd1[Nn * HEADS];
__device__ float g_fs1[Nn * HEADS];
__device__ float g_fd2[Nn];
__device__ float g_fs2[Nn];
__device__ float g_lg1[(size_t)Ee * HEADS]; // CSR-ordered logits -> att (in place)
__device__ float g_lg2[Ee];                 // CSR-ordered
__device__ float g_mx1[Nn * HEADS];
__device__ float g_iv1[Nn * HEADS];
__device__ float g_mx2[Nn];
__device__ float g_iv2[Nn];
__device__ int   g_cnt[Nn];
__device__ int   g_off[Nn + 1];
__device__ int   g_cur[Nn];
__device__ int   g_pos [Ee];   // edge e -> CSR slot p
__device__ int   g_rows[Ee];   // CSR slot p -> dst node
__device__ int   g_cols[Ee];   // CSR slot p -> src node

// bf16 hi/lo operands for tensor-core GEMMs
__device__ __align__(256) __nv_bfloat16 g_xhi[(size_t)Mpad * 512];
__device__ __align__(256) __nv_bfloat16 g_xlo[(size_t)Mpad * 512];
__device__ __align__(256) __nv_bfloat16 g_bhi[512 * 512];   // W1t[n][k]
__device__ __align__(256) __nv_bfloat16 g_blo[512 * 512];
__device__ __align__(256) __nv_bfloat16 g_h1hi[(size_t)Mpad * 512];
__device__ __align__(256) __nv_bfloat16 g_h1lo[(size_t)Mpad * 512];
__device__ __align__(256) __nv_bfloat16 g_b2hi[64 * 512];   // W_out_t[n][k]
__device__ __align__(256) __nv_bfloat16 g_b2lo[64 * 512];

// ---------------- small PTX helpers ----------------------------------------
__device__ __forceinline__ uint32_t smem_u32(const void* p) {
    uint32_t a;
    asm("{ .reg .u64 t; cvta.to.shared.u64 t, %1; cvt.u32.u64 %0, t; }" : "=r"(a) : "l"(p));
    return a;
}
__device__ __forceinline__ void cpa16(uint32_t dst, const void* src) {
    asm volatile("cp.async.cg.shared.global [%0], [%1], 16;" :: "r"(dst), "l"(src));
}
__device__ __forceinline__ void cpa_commit() {
    asm volatile("cp.async.commit_group;" ::: "memory");
}
template <int N> __device__ __forceinline__ void cpa_wait() {
    asm volatile("cp.async.wait_group %0;" :: "n"(N) : "memory");
}
__device__ __forceinline__ void ldm4(uint32_t* r, uint32_t addr) {
    asm volatile("ldmatrix.sync.aligned.m8n8.x4.shared.b16 {%0,%1,%2,%3}, [%4];"
                 : "=r"(r[0]), "=r"(r[1]), "=r"(r[2]), "=r"(r[3]) : "r"(addr));
}
__device__ __forceinline__ void mma16816(float* c, const uint32_t* a,
                                         uint32_t b0, uint32_t b1) {
    asm volatile(
        "mma.sync.aligned.m16n8k16.row.col.f32.bf16.bf16.f32 "
        "{%0,%1,%2,%3}, {%4,%5,%6,%7}, {%8,%9}, {%0,%1,%2,%3};"
        : "+f"(c[0]), "+f"(c[1]), "+f"(c[2]), "+f"(c[3])
        : "r"(a[0]), "r"(a[1]), "r"(a[2]), "r"(a[3]), "r"(b0), "r"(b1));
}

// ---------------- bf16 hi/lo conversion kernels ------------------------------
__global__ void k_cvt_x(const float* __restrict__ x) {
    long long i4 = (long long)blockIdx.x * blockDim.x + threadIdx.x; // float4 idx
    if (i4 >= (long long)Mpad * 128) return;
    long long row = i4 >> 7;
    float4 v = make_float4(0.f, 0.f, 0.f, 0.f);
    if (row < Nn) v = ((const float4*)x)[i4];
    __nv_bfloat16 h0 = __float2bfloat16_rn(v.x);
    __nv_bfloat16 h1 = __float2bfloat16_rn(v.y);
    __nv_bfloat16 h2 = __float2bfloat16_rn(v.z);
    __nv_bfloat16 h3 = __float2bfloat16_rn(v.w);
    __nv_bfloat16 l0 = __float2bfloat16_rn(v.x - __bfloat162float(h0));
    __nv_bfloat16 l1 = __float2bfloat16_rn(v.y - __bfloat162float(h1));
    __nv_bfloat16 l2 = __float2bfloat16_rn(v.z - __bfloat162float(h2));
    __nv_bfloat16 l3 = __float2bfloat16_rn(v.w - __bfloat162float(h3));
    __nv_bfloat16* ph = g_xhi + i4 * 4;
    __nv_bfloat16* pl = g_xlo + i4 * 4;
    ph[0] = h0; ph[1] = h1; ph[2] = h2; ph[3] = h3;
    pl[0] = l0; pl[1] = l1; pl[2] = l2; pl[3] = l3;
}

__global__ void k_cvt_w(const float* __restrict__ W) {
    int idx = blockIdx.x * blockDim.x + threadIdx.x;  // n*512 + k
    if (idx >= 512 * 512) return;
    int n = idx >> 9, k = idx & 511;
    float v = W[(size_t)(n >> 6) * (512 * 64) + (size_t)k * 64 + (n & 63)];
    __nv_bfloat16 h = __float2bfloat16_rn(v);
    __nv_bfloat16 l = __float2bfloat16_rn(v - __bfloat162float(h));
    g_bhi[idx] = h;
    g_blo[idx] = l;
}

__global__ void k_cvt_w2(const float* __restrict__ W_out) {
    int idx = blockIdx.x * blockDim.x + threadIdx.x;  // n*512 + k
    if (idx >= 64 * 512) return;
    int n = idx >> 9, k = idx & 511;
    float v = W_out[(size_t)k * 64 + n];
    __nv_bfloat16 h = __float2bfloat16_rn(v);
    __nv_bfloat16 l = __float2bfloat16_rn(v - __bfloat162float(h));
    g_b2hi[idx] = h;
    g_b2lo[idx] = l;
}

__global__ void k_pad_h1() {
    int idx = blockIdx.x * blockDim.x + threadIdx.x;   // (Mpad-Nn)*512
    if (idx >= (Mpad - Nn) * 512) return;
    size_t o = (size_t)Nn * 512 + idx;
    g_h1hi[o] = __float2bfloat16_rn(0.f);
    g_h1lo[o] = __float2bfloat16_rn(0.f);
}

// ---------------- HMMA GEMM1: g_Wh[M,512] = x @ Wcat ------------------------
#define A_HI 0
#define A_LO 10240
#define B_HI 20480
#define B_LO 30720
#define STAGE 40960
#define SMEM_GEMM_TOTAL (2 * STAGE)

__device__ __forceinline__ void load_stage(uint32_t s, int t, int m0, int n0, int kc) {
    int k0 = kc * 32;
#pragma unroll
    for (int i = 0; i < 2; i++) {
        int idx = t + i * 256;          // 0..511
        int r = idx >> 2;               // row 0..127
        int c = idx & 3;                // 16B chunk
        uint32_t d = s + (uint32_t)(r * 80 + c * 16);
        size_t sa = (size_t)(m0 + r) * 512 + k0 + c * 8;
        size_t sbg = (size_t)(n0 + r) * 512 + k0 + c * 8;
        cpa16(d + A_HI, g_xhi + sa);
        cpa16(d + A_LO, g_xlo + sa);
        cpa16(d + B_HI, g_bhi + sbg);
        cpa16(d + B_LO, g_blo + sbg);
    }
    cpa_commit();
}

__global__ void __launch_bounds__(256) k_gemm1_mma() {
    extern __shared__ char smem[];
    uint32_t sb = smem_u32(smem);
    const int t = threadIdx.x;
    const int lane = t & 31, w = t >> 5;
    const int wm = w & 3, wn = w >> 2;          // warp grid 4(m) x 2(n)
    const int m0 = blockIdx.x * 128, n0 = blockIdx.y * 128;

    float acc[2][8][4];
#pragma unroll
    for (int mf = 0; mf < 2; mf++)
#pragma unroll
        for (int nf = 0; nf < 8; nf++)
#pragma unroll
            for (int q = 0; q < 4; q++) acc[mf][nf][q] = 0.f;

    load_stage(sb, t, m0, n0, 0);

    const int a_row = wm * 32 + (lane & 15);
    const int a_colb = (lane >> 4) * 8;
    const int b_row = wn * 64 + ((lane >> 4) & 1) * 8 + (lane & 7);
    const int b_colb = ((lane >> 3) & 1) * 8;

    for (int kc = 0; kc < 16; kc++) {
        uint32_t s = sb + (uint32_t)(kc & 1) * STAGE;
        if (kc + 1 < 16) load_stage(sb + (uint32_t)((kc + 1) & 1) * STAGE, t, m0, n0, kc + 1);
        if (kc + 1 < 16) { cpa_wait<1>(); } else { cpa_wait<0>(); }
        __syncthreads();

#pragma unroll
        for (int ks = 0; ks < 2; ks++) {
            uint32_t ah[2][4], al[2][4];
#pragma unroll
            for (int mf = 0; mf < 2; mf++) {
                uint32_t ad = s + (uint32_t)((a_row + mf * 16) * 80 + (ks * 16 + a_colb) * 2);
                ldm4(ah[mf], ad + A_HI);
                ldm4(al[mf], ad + A_LO);
            }
            uint32_t bh[4][4], bl[4][4];
#pragma unroll
            for (int nb = 0; nb < 4; nb++) {
                uint32_t bd = s + (uint32_t)((b_row + nb * 16) * 80 + (ks * 16 + b_colb) * 2);
                ldm4(bh[nb], bd + B_HI);
                ldm4(bl[nb], bd + B_LO);
            }
#pragma unroll
            for (int mf = 0; mf < 2; mf++)
#pragma unroll
                for (int nb = 0; nb < 4; nb++)
#pragma unroll
                    for (int half = 0; half < 2; half++) {
                        float* c = acc[mf][nb * 2 + half];
                        mma16816(c, ah[mf], bh[nb][half * 2], bh[nb][half * 2 + 1]);
                        mma16816(c, ah[mf], bl[nb][half * 2], bl[nb][half * 2 + 1]);
                        mma16816(c, al[mf], bh[nb][half * 2], bh[nb][half * 2 + 1]);
                    }
        }
        __syncthreads();
    }

#pragma unroll
    for (int mf = 0; mf < 2; mf++) {
        int r0 = m0 + wm * 32 + mf * 16 + (lane >> 2);
#pragma unroll
        for (int nf = 0; nf < 8; nf++) {
            int cc = n0 + wn * 64 + nf * 8 + (lane & 3) * 2;
            float* c = acc[mf][nf];
            if (r0 < Nn)
                *(float2*)(g_Wh + (size_t)r0 * 512 + cc) = make_float2(c[0], c[1]);
            if (r0 + 8 < Nn)
                *(float2*)(g_Wh + (size_t)(r0 + 8) * 512 + cc) = make_float2(c[2], c[3]);
        }
    }
}

// ---------------- HMMA GEMM2: g_Wh2[M,64] = h1 @ W_out ----------------------
#define A2_HI 0
#define A2_LO 10240
#define B2_HI 20480
#define B2_LO 25600
#define STAGE2 30720
#define SMEM_GEMM2_TOTAL (2 * STAGE2)

__device__ __forceinline__ void load_stage2(uint32_t s, int t, int m0, int kc) {
    int k0 = kc * 32;
#pragma unroll
    for (int i = 0; i < 2; i++) {
        int idx = t + i * 256;          // 0..511
        int r = idx >> 2;
        int c = idx & 3;
        uint32_t d = s + (uint32_t)(r * 80 + c * 16);
        size_t sa = (size_t)(m0 + r) * 512 + k0 + c * 8;
        cpa16(d + A2_HI, g_h1hi + sa);
        cpa16(d + A2_LO, g_h1lo + sa);
    }
    if (t < 256) {
        int r = t >> 2, c = t & 3;
        uint32_t d = s + (uint32_t)(r * 80 + c * 16);
        size_t sbg = (size_t)r * 512 + k0 + c * 8;
        cpa16(d + B2_HI, g_b2hi + sbg);
        cpa16(d + B2_LO, g_b2lo + sbg);
    }
    cpa_commit();
}

__global__ void __launch_bounds__(256) k_gemm2_mma() {
    extern __shared__ char smem[];
    uint32_t sb = smem_u32(smem);
    const int t = threadIdx.x;
    const int lane = t & 31, w = t >> 5;
    const int wm = w & 3, wn = w >> 2;          // 4(m) x 2(n), warp tile 32x32
    const int m0 = blockIdx.x * 128;

    float acc[2][4][4];
#pragma unroll
    for (int mf = 0; mf < 2; mf++)
#pragma unroll
        for (int nf = 0; nf < 4; nf++)
#pragma unroll
            for (int q = 0; q < 4; q++) acc[mf][nf][q] = 0.f;

    load_stage2(sb, t, m0, 0);

    const int a_row = wm * 32 + (lane & 15);
    const int a_colb = (lane >> 4) * 8;
    const int b_row = wn * 32 + ((lane >> 4) & 1) * 8 + (lane & 7);
    const int b_colb = ((lane >> 3) & 1) * 8;

    for (int kc = 0; kc < 16; kc++) {
        uint32_t s = sb + (uint32_t)(kc & 1) * STAGE2;
        if (kc + 1 < 16) load_stage2(sb + (uint32_t)((kc + 1) & 1) * STAGE2, t, m0, kc + 1);
        if (kc + 1 < 16) { cpa_wait<1>(); } else { cpa_wait<0>(); }
        __syncthreads();

#pragma unroll
        for (int ks = 0; ks < 2; ks++) {
            uint32_t ah[2][4], al[2][4];
#pragma unroll
            for (int mf = 0; mf < 2; mf++) {
                uint32_t ad = s + (uint32_t)((a_row + mf * 16) * 80 + (ks * 16 + a_colb) * 2);
                ldm4(ah[mf], ad + A2_HI);
                ldm4(al[mf], ad + A2_LO);
            }
            uint32_t bh[2][4], bl[2][4];
#pragma unroll
            for (int nb = 0; nb < 2; nb++) {
                uint32_t bd = s + (uint32_t)((b_row + nb * 16) * 80 + (ks * 16 + b_colb) * 2);
                ldm4(bh[nb], bd + B2_HI);
                ldm4(bl[nb], bd + B2_LO);
            }
#pragma unroll
            for (int mf = 0; mf < 2; mf++)
#pragma unroll
                for (int nb = 0; nb < 2; nb++)
#pragma unroll
                    for (int half = 0; half < 2; half++) {
                        float* c = acc[mf][nb * 2 + half];
                        mma16816(c, ah[mf], bh[nb][half * 2], bh[nb][half * 2 + 1]);
                        mma16816(c, ah[mf], bl[nb][half * 2], bl[nb][half * 2 + 1]);
                        mma16816(c, al[mf], bh[nb][half * 2], bh[nb][half * 2 + 1]);
                    }
        }
        __syncthreads();
    }

#pragma unroll
    for (int mf = 0; mf < 2; mf++) {
        int r0 = m0 + wm * 32 + mf * 16 + (lane >> 2);
#pragma unroll
        for (int nf = 0; nf < 4; nf++) {
            int cc = wn * 32 + nf * 8 + (lane & 3) * 2;
            float* c = acc[mf][nf];
            if (r0 < Nn)
                *(float2*)(g_Wh2 + (size_t)r0 * 64 + cc) = make_float2(c[0], c[1]);
            if (r0 + 8 < Nn)
                *(float2*)(g_Wh2 + (size_t)(r0 + 8) * 64 + cc) = make_float2(c[2], c[3]);
        }
    }
}

// ---------------- CSR build ------------------------------------------------
__global__ void k_zero_cnt() {
    int i = blockIdx.x * blockDim.x + threadIdx.x;
    if (i < Nn) g_cnt[i] = 0;
}

__global__ void k_hist(const int* __restrict__ row) {
    int e = blockIdx.x * blockDim.x + threadIdx.x;
    if (e < Ee) atomicAdd(&g_cnt[row[e]], 1);
}

__global__ void k_scan() {
    __shared__ int sh[2][1024];
    __shared__ int s_base;
    int t = threadIdx.x;
    if (t == 0) s_base = 0;
    __syncthreads();
    for (int start = 0; start < Nn; start += 1024) {
        int i = start + t;
        int v = (i < Nn) ? g_cnt[i] : 0;
        int orig = v;
        int pi = 0;
        sh[0][t] = v;
        __syncthreads();
        for (int s = 1; s < 1024; s <<= 1) {
            int w = sh[pi][t];
            if (t >= s) w += sh[pi][t - s];
            sh[pi ^ 1][t] = w;
            pi ^= 1;
            __syncthreads();
        }
        int incl = sh[pi][t];
        int base = s_base;
        if (i < Nn) {
            int ex = base + incl - orig;
            g_off[i] = ex;
            g_cur[i] = ex;
        }
        __syncthreads();
        if (t == 1023) s_base = base + incl;
        __syncthreads();
    }
    if (t == 0) g_off[Nn] = s_base;
}

__global__ void k_scatter(const int* __restrict__ row, const int* __restrict__ col) {
    int e = blockIdx.x * blockDim.x + threadIdx.x;
    if (e < Ee) {
        int r = row[e];
        int p = atomicAdd(&g_cur[r], 1);
        g_pos[e]  = p;
        g_rows[p] = r;
        g_cols[p] = col[e];
    }
}

// ---------------- layer1: f_dst/f_src per node ------------------------------
__global__ void k_f1(const float* __restrict__ a) {
    int i = blockIdx.x;
    int t = threadIdx.x;  // 256
    __shared__ float sd[512], ss[512];
    const float* whr = g_Wh + (size_t)i * 512;
    float v0 = whr[t], v1 = whr[t + 256];
    int h0 = t >> 6, j0 = t & 63;
    int idx1 = t + 256;
    int h1 = idx1 >> 6, j1 = idx1 & 63;
    sd[t]      = v0 * a[h0 * 128 + j0];
    ss[t]      = v0 * a[h0 * 128 + 64 + j0];
    sd[idx1]   = v1 * a[h1 * 128 + j1];
    ss[idx1]   = v1 * a[h1 * 128 + 64 + j1];
    __syncthreads();
    if (t < 16) {
        int h = t & 7;
        const float* buf = (t < 8) ? sd : ss;
        float s = 0.f;
#pragma unroll
        for (int j = 0; j < 64; j++) s += buf[h * 64 + j];
        if (t < 8) g_fd1[i * 8 + h] = s;
        else       g_fs1[i * 8 + h] = s;
    }
}

// ---------------- layer1: edge logits -> CSR slots --------------------------
__global__ void k_logits1(const int* __restrict__ row, const int* __restrict__ col) {
    int e = blockIdx.x * blockDim.x + threadIdx.x;
    if (e >= Ee) return;
    int r = row[e], c = col[e];
    float4 d0 = *(const float4*)(g_fd1 + r * 8);
    float4 d1 = *(const float4*)(g_fd1 + r * 8 + 4);
    float4 s0 = *(const float4*)(g_fs1 + c * 8);
    float4 s1 = *(const float4*)(g_fs1 + c * 8 + 4);
    float v[8] = {d0.x + s0.x, d0.y + s0.y, d0.z + s0.z, d0.w + s0.w,
                  d1.x + s1.x, d1.y + s1.y, d1.z + s1.z, d1.w + s1.w};
#pragma unroll
    for (int h = 0; h < 8; h++) v[h] = v[h] > 0.f ? v[h] : ALPHA * v[h];
    size_t p = (size_t)g_pos[e] * 8;
    *(float4*)(g_lg1 + p)     = make_float4(v[0], v[1], v[2], v[3]);
    *(float4*)(g_lg1 + p + 4) = make_float4(v[4], v[5], v[6], v[7]);
}

// ---------------- layer1: per (node,head) max + sumexp (warp/node) ----------
__global__ void k_maxsum1() {
    int gw = (blockIdx.x * blockDim.x + threadIdx.x) >> 5;  // node
    if (gw >= Nn) return;
    int lane = threadIdx.x & 31;
    int h = lane & 7, sub = lane >> 3;
    int o = g_off[gw], oe = g_off[gw + 1];
    float mx = -3.4e38f;
    for (int p = o + sub; p < oe; p += 4)
        mx = fmaxf(mx, g_lg1[(size_t)p * 8 + h]);
    mx = fmaxf(mx, __shfl_xor_sync(0xffffffffu, mx, 8));
    mx = fmaxf(mx, __shfl_xor_sync(0xffffffffu, mx, 16));
    float s = 0.f;
    for (int p = o + sub; p < oe; p += 4)
        s += __expf(g_lg1[(size_t)p * 8 + h] - mx);
    s += __shfl_xor_sync(0xffffffffu, s, 8);
    s += __shfl_xor_sync(0xffffffffu, s, 16);
    if (lane < 8) {
        float iv = (oe > o) ? 1.f / fmaxf(s, 1e-16f) : 0.f;
        g_mx1[gw * 8 + lane] = (oe > o) ? mx : 0.f;
        g_iv1[gw * 8 + lane] = iv;
    }
}

// ---------------- layer1: normalize (CSR order) ------------------------------
__global__ void k_att1() {
    long long idx = (long long)blockIdx.x * blockDim.x + threadIdx.x;
    if (idx >= (long long)Ee * 8) return;
    int p = (int)(idx >> 3), h = (int)(idx & 7);
    int i = g_rows[p];
    g_lg1[idx] = __expf(g_lg1[idx] - g_mx1[i * 8 + h]) * g_iv1[i * 8 + h];
}

// ---------------- layer1: aggregation + ELU -> bf16 hi/lo --------------------
__global__ void __launch_bounds__(256) k_agg1() {
    int i = blockIdx.x;
    int t = threadIdx.x;
    int o = g_off[i], oe = g_off[i + 1];
    int ha = t >> 6;
    int hb = ha + 4;
    float acc0 = 0.f, acc1 = 0.f;
    for (int p = o; p < oe; p++) {
        int c = g_cols[p];
        float w0 = g_lg1[(size_t)p * 8 + ha];
        float w1 = g_lg1[(size_t)p * 8 + hb];
        const float* whc = g_Wh + (size_t)c * 512;
        acc0 = fmaf(w0, whc[t], acc0);
        acc1 = fmaf(w1, whc[t + 256], acc1);
    }
    float v0 = acc0 > 0.f ? acc0 : (__expf(acc0) - 1.f);
    float v1 = acc1 > 0.f ? acc1 : (__expf(acc1) - 1.f);
    size_t base = (size_t)i * 512;
    __nv_bfloat16 h0 = __float2bfloat16_rn(v0);
    __nv_bfloat16 h1 = __float2bfloat16_rn(v1);
    g_h1hi[base + t]       = h0;
    g_h1hi[base + t + 256] = h1;
    g_h1lo[base + t]       = __float2bfloat16_rn(v0 - __bfloat162float(h0));
    g_h1lo[base + t + 256] = __float2bfloat16_rn(v1 - __bfloat162float(h1));
}

// ---------------- layer2 ------------------------------------------------------
__global__ void k_f2(const float* __restrict__ a_out) {
    int gt = blockIdx.x * blockDim.x + threadIdx.x;
    int w  = gt >> 5;
    int ln = gt & 31;
    if (w >= Nn) return;
    float v0 = g_Wh2[(size_t)w * 64 + ln];
    float v1 = g_Wh2[(size_t)w * 64 + 32 + ln];
    float pd = v0 * a_out[ln]      + v1 * a_out[ln + 32];
    float ps = v0 * a_out[64 + ln] + v1 * a_out[96 + ln];
#pragma unroll
    for (int s = 16; s > 0; s >>= 1) {
        pd += __shfl_down_sync(0xffffffffu, pd, s);
        ps += __shfl_down_sync(0xffffffffu, ps, s);
    }
    if (ln == 0) { g_fd2[w] = pd; g_fs2[w] = ps; }
}

__global__ void k_logits2(const int* __restrict__ row, const int* __restrict__ col) {
    int e = blockIdx.x * blockDim.x + threadIdx.x;
    if (e >= Ee) return;
    float v = g_fd2[row[e]] + g_fs2[col[e]];
    g_lg2[g_pos[e]] = v > 0.f ? v : ALPHA * v;
}

__global__ void k_maxsum2() {
    int gw = (blockIdx.x * blockDim.x + threadIdx.x) >> 5;
    if (gw >= Nn) return;
    int lane = threadIdx.x & 31;
    int o = g_off[gw], oe = g_off[gw + 1];
    float mx = -3.4e38f;
    for (int p = o + lane; p < oe; p += 32) mx = fmaxf(mx, g_lg2[p]);
#pragma unroll
    for (int s = 16; s > 0; s >>= 1) mx = fmaxf(mx, __shfl_xor_sync(0xffffffffu, mx, s));
    float sum = 0.f;
    for (int p = o + lane; p < oe; p += 32) sum += __expf(g_lg2[p] - mx);
#pragma unroll
    for (int s = 16; s > 0; s >>= 1) sum += __shfl_xor_sync(0xffffffffu, sum, s);
    if (lane == 0) {
        g_mx2[gw] = (oe > o) ? mx : 0.f;
        g_iv2[gw] = (oe > o) ? 1.f / fmaxf(sum, 1e-16f) : 0.f;
    }
}

__global__ void k_att2() {
    int p = blockIdx.x * blockDim.x + threadIdx.x;
    if (p >= Ee) return;
    int i = g_rows[p];
    g_lg2[p] = __expf(g_lg2[p] - g_mx2[i]) * g_iv2[i];
}

__global__ void __launch_bounds__(64) k_agg2(float* __restrict__ out) {
    int i = blockIdx.x;
    int t = threadIdx.x;
    int o = g_off[i], oe = g_off[i + 1];
    float acc = 0.f;
    for (int p = o; p < oe; p++) {
        int c = g_cols[p];
        acc = fmaf(g_lg2[p], g_Wh2[(size_t)c * 64 + t], acc);
    }
    out[(size_t)i * 64 + t] = acc;
}

// ---------------- launch -----------------------------------------------------
extern "C" void kernel_launch(void* const* d_in, const int* in_sizes, int n_in,
                              void* d_out, int out_size) {
    const float* x     = (const float*)d_in[0];
    const int*   row   = (const int*)  d_in[1];
    const int*   col   = (const int*)  d_in[2];
    const float* W     = (const float*)d_in[3];
    const float* a     = (const float*)d_in[4];
    const float* W_out = (const float*)d_in[5];
    const float* a_out = (const float*)d_in[6];
    float* out = (float*)d_out;

    const int EB = (Ee + 255) / 256;

    cudaFuncSetAttribute(k_gemm1_mma, cudaFuncAttributeMaxDynamicSharedMemorySize,
                         SMEM_GEMM_TOTAL);
    cudaFuncSetAttribute(k_gemm2_mma, cudaFuncAttributeMaxDynamicSharedMemorySize,
                         SMEM_GEMM2_TOTAL);

    // operand conversion for tensor-core GEMMs
    k_cvt_x<<<(int)(((long long)Mpad * 128 + 255) / 256), 256>>>(x);
    k_cvt_w<<<(512 * 512 + 255) / 256, 256>>>(W);
    k_cvt_w2<<<(64 * 512 + 255) / 256, 256>>>(W_out);
    k_pad_h1<<<((Mpad - Nn) * 512 + 255) / 256, 256>>>();

    // CSR build (counting sort by destination node)
    k_zero_cnt<<<(Nn + 255) / 256, 256>>>();
    k_hist<<<EB, 256>>>(row);
    k_scan<<<1, 1024>>>();
    k_scatter<<<EB, 256>>>(row, col);

    // layer 1
    k_gemm1_mma<<<dim3(Mpad / 128, 4), 256, SMEM_GEMM_TOTAL>>>();
    k_f1<<<Nn, 256>>>(a);
    k_logits1<<<EB, 256>>>(row, col);
    k_maxsum1<<<(Nn * 32 + 255) / 256, 256>>>();
    k_att1<<<(int)(((long long)Ee * 8 + 255) / 256), 256>>>();
    k_agg1<<<Nn, 256>>>();

    // layer 2
    k_gemm2_mma<<<Mpad / 128, 256, SMEM_GEMM2_TOTAL>>>();
    k_f2<<<(Nn * 32 + 255) / 256, 256>>>(a_out);
    k_logits2<<<EB, 256>>>(row, col);
    k_maxsum2<<<(Nn * 32 + 255) / 256, 256>>>();
    k_att2<<<(Ee + 255) / 256, 256>>>();
    k_agg2<<<Nn, 64>>>(out);
}

// round 6
// speedup vs baseline: 1.6902x; 1.0828x over previous
#include <cuda_runtime.h>
#include <cuda_bf16.h>
#include <stdint.h>
#include <math.h>

// Problem constants
#define Nn    50000
#define Mpad  50048           // padded rows for 128-tiles
#define Ee    800000
#define FEAT  512
#define HEADS 8
#define HID   64
#define C1    512    // HEADS*HID
#define NC    64     // NCLASS
#define ALPHA 0.2f

// ---------------- scratch (device globals; no allocation allowed) ----------
__device__ float g_Wh [(size_t)Nn * C1];   // layer1 Wh (concat heads)
__device__ float g_Wh2[(size_t)Nn * NC];   // layer2 Wh
__device__ float g_fd1[Nn * HEADS];
__device__ float g_fs1[Nn * HEADS];
__device__ float g_fd2[Nn];
__device__ float g_fs2[Nn];
__device__ float g_lg1[(size_t)Ee * HEADS]; // CSR-ordered raw logits
__device__ float g_lg2[Ee];                 // CSR-ordered raw logits
__device__ float g_mx1[Nn * HEADS];
__device__ float g_iv1[Nn * HEADS];
__device__ float g_mx2[Nn];
__device__ float g_iv2[Nn];
__device__ int   g_cnt[Nn];
__device__ int   g_off[Nn + 1];
__device__ int   g_cur[Nn];
__device__ int   g_pos [Ee];   // edge e -> CSR slot p
__device__ int   g_rows[Ee];   // CSR slot p -> dst node (kept for maxsum use)
__device__ int   g_cols[Ee];   // CSR slot p -> src node

// bf16 hi/lo operands for tensor-core GEMMs
__device__ __align__(256) __nv_bfloat16 g_xhi[(size_t)Mpad * 512];
__device__ __align__(256) __nv_bfloat16 g_xlo[(size_t)Mpad * 512];
__device__ __align__(256) __nv_bfloat16 g_bhi[512 * 512];   // W1t[n][k]
__device__ __align__(256) __nv_bfloat16 g_blo[512 * 512];
__device__ __align__(256) __nv_bfloat16 g_h1hi[(size_t)Mpad * 512];  // pad rows stay 0
__device__ __align__(256) __nv_bfloat16 g_h1lo[(size_t)Mpad * 512];
__device__ __align__(256) __nv_bfloat16 g_b2hi[64 * 512];   // W_out_t[n][k]
__device__ __align__(256) __nv_bfloat16 g_b2lo[64 * 512];

// ---------------- small PTX helpers ----------------------------------------
__device__ __forceinline__ uint32_t smem_u32(const void* p) {
    uint32_t a;
    asm("{ .reg .u64 t; cvta.to.shared.u64 t, %1; cvt.u32.u64 %0, t; }" : "=r"(a) : "l"(p));
    return a;
}
__device__ __forceinline__ void cpa16(uint32_t dst, const void* src) {
    asm volatile("cp.async.cg.shared.global [%0], [%1], 16;" :: "r"(dst), "l"(src));
}
__device__ __forceinline__ void cpa_commit() {
    asm volatile("cp.async.commit_group;" ::: "memory");
}
template <int N> __device__ __forceinline__ void cpa_wait() {
    asm volatile("cp.async.wait_group %0;" :: "n"(N) : "memory");
}
__device__ __forceinline__ void ldm4(uint32_t* r, uint32_t addr) {
    asm volatile("ldmatrix.sync.aligned.m8n8.x4.shared.b16 {%0,%1,%2,%3}, [%4];"
                 : "=r"(r[0]), "=r"(r[1]), "=r"(r[2]), "=r"(r[3]) : "r"(addr));
}
__device__ __forceinline__ void mma16816(float* c, const uint32_t* a,
                                         uint32_t b0, uint32_t b1) {
    asm volatile(
        "mma.sync.aligned.m16n8k16.row.col.f32.bf16.bf16.f32 "
        "{%0,%1,%2,%3}, {%4,%5,%6,%7}, {%8,%9}, {%0,%1,%2,%3};"
        : "+f"(c[0]), "+f"(c[1]), "+f"(c[2]), "+f"(c[3])
        : "r"(a[0]), "r"(a[1]), "r"(a[2]), "r"(a[3]), "r"(b0), "r"(b1));
}

// ---------------- bf16 hi/lo conversion kernels ------------------------------
__global__ void k_cvt_x(const float* __restrict__ x) {
    long long i4 = (long long)blockIdx.x * blockDim.x + threadIdx.x; // float4 idx
    if (i4 >= (long long)Mpad * 128) return;
    long long row = i4 >> 7;
    float4 v = make_float4(0.f, 0.f, 0.f, 0.f);
    if (row < Nn) v = ((const float4*)x)[i4];
    __nv_bfloat16 h0 = __float2bfloat16_rn(v.x);
    __nv_bfloat16 h1 = __float2bfloat16_rn(v.y);
    __nv_bfloat16 h2 = __float2bfloat16_rn(v.z);
    __nv_bfloat16 h3 = __float2bfloat16_rn(v.w);
    __nv_bfloat16 l0 = __float2bfloat16_rn(v.x - __bfloat162float(h0));
    __nv_bfloat16 l1 = __float2bfloat16_rn(v.y - __bfloat162float(h1));
    __nv_bfloat16 l2 = __float2bfloat16_rn(v.z - __bfloat162float(h2));
    __nv_bfloat16 l3 = __float2bfloat16_rn(v.w - __bfloat162float(h3));
    __nv_bfloat16* ph = g_xhi + i4 * 4;
    __nv_bfloat16* pl = g_xlo + i4 * 4;
    ph[0] = h0; ph[1] = h1; ph[2] = h2; ph[3] = h3;
    pl[0] = l0; pl[1] = l1; pl[2] = l2; pl[3] = l3;
}

__global__ void k_cvt_w(const float* __restrict__ W) {
    int idx = blockIdx.x * blockDim.x + threadIdx.x;  // n*512 + k
    if (idx >= 512 * 512) return;
    int n = idx >> 9, k = idx & 511;
    float v = W[(size_t)(n >> 6) * (512 * 64) + (size_t)k * 64 + (n & 63)];
    __nv_bfloat16 h = __float2bfloat16_rn(v);
    __nv_bfloat16 l = __float2bfloat16_rn(v - __bfloat162float(h));
    g_bhi[idx] = h;
    g_blo[idx] = l;
}

__global__ void k_cvt_w2(const float* __restrict__ W_out) {
    int idx = blockIdx.x * blockDim.x + threadIdx.x;  // n*512 + k
    if (idx >= 64 * 512) return;
    int n = idx >> 9, k = idx & 511;
    float v = W_out[(size_t)k * 64 + n];
    __nv_bfloat16 h = __float2bfloat16_rn(v);
    __nv_bfloat16 l = __float2bfloat16_rn(v - __bfloat162float(h));
    g_b2hi[idx] = h;
    g_b2lo[idx] = l;
}

// ---------------- HMMA GEMM1: g_Wh[M,512] = x @ Wcat ------------------------
#define A_HI 0
#define A_LO 10240
#define B_HI 20480
#define B_LO 30720
#define STAGE 40960
#define SMEM_GEMM_TOTAL (2 * STAGE)

__device__ __forceinline__ void load_stage(uint32_t s, int t, int m0, int n0, int kc) {
    int k0 = kc * 32;
#pragma unroll
    for (int i = 0; i < 2; i++) {
        int idx = t + i * 256;          // 0..511
        int r = idx >> 2;               // row 0..127
        int c = idx & 3;                // 16B chunk
        uint32_t d = s + (uint32_t)(r * 80 + c * 16);
        size_t sa = (size_t)(m0 + r) * 512 + k0 + c * 8;
        size_t sbg = (size_t)(n0 + r) * 512 + k0 + c * 8;
        cpa16(d + A_HI, g_xhi + sa);
        cpa16(d + A_LO, g_xlo + sa);
        cpa16(d + B_HI, g_bhi + sbg);
        cpa16(d + B_LO, g_blo + sbg);
    }
    cpa_commit();
}

__global__ void __launch_bounds__(256) k_gemm1_mma() {
    extern __shared__ char smem[];
    uint32_t sb = smem_u32(smem);
    const int t = threadIdx.x;
    const int lane = t & 31, w = t >> 5;
    const int wm = w & 3, wn = w >> 2;          // warp grid 4(m) x 2(n)
    const int m0 = blockIdx.x * 128, n0 = blockIdx.y * 128;

    float acc[2][8][4];
#pragma unroll
    for (int mf = 0; mf < 2; mf++)
#pragma unroll
        for (int nf = 0; nf < 8; nf++)
#pragma unroll
            for (int q = 0; q < 4; q++) acc[mf][nf][q] = 0.f;

    load_stage(sb, t, m0, n0, 0);

    const int a_row = wm * 32 + (lane & 15);
    const int a_colb = (lane >> 4) * 8;
    const int b_row = wn * 64 + ((lane >> 4) & 1) * 8 + (lane & 7);
    const int b_colb = ((lane >> 3) & 1) * 8;

    for (int kc = 0; kc < 16; kc++) {
        uint32_t s = sb + (uint32_t)(kc & 1) * STAGE;
        if (kc + 1 < 16) load_stage(sb + (uint32_t)((kc + 1) & 1) * STAGE, t, m0, n0, kc + 1);
        if (kc + 1 < 16) { cpa_wait<1>(); } else { cpa_wait<0>(); }
        __syncthreads();

#pragma unroll
        for (int ks = 0; ks < 2; ks++) {
            uint32_t ah[2][4], al[2][4];
#pragma unroll
            for (int mf = 0; mf < 2; mf++) {
                uint32_t ad = s + (uint32_t)((a_row + mf * 16) * 80 + (ks * 16 + a_colb) * 2);
                ldm4(ah[mf], ad + A_HI);
                ldm4(al[mf], ad + A_LO);
            }
            uint32_t bh[4][4], bl[4][4];
#pragma unroll
            for (int nb = 0; nb < 4; nb++) {
                uint32_t bd = s + (uint32_t)((b_row + nb * 16) * 80 + (ks * 16 + b_colb) * 2);
                ldm4(bh[nb], bd + B_HI);
                ldm4(bl[nb], bd + B_LO);
            }
#pragma unroll
            for (int mf = 0; mf < 2; mf++)
#pragma unroll
                for (int nb = 0; nb < 4; nb++)
#pragma unroll
                    for (int half = 0; half < 2; half++) {
                        float* c = acc[mf][nb * 2 + half];
                        mma16816(c, ah[mf], bh[nb][half * 2], bh[nb][half * 2 + 1]);
                        mma16816(c, ah[mf], bl[nb][half * 2], bl[nb][half * 2 + 1]);
                        mma16816(c, al[mf], bh[nb][half * 2], bh[nb][half * 2 + 1]);
                    }
        }
        __syncthreads();
    }

#pragma unroll
    for (int mf = 0; mf < 2; mf++) {
        int r0 = m0 + wm * 32 + mf * 16 + (lane >> 2);
#pragma unroll
        for (int nf = 0; nf < 8; nf++) {
            int cc = n0 + wn * 64 + nf * 8 + (lane & 3) * 2;
            float* c = acc[mf][nf];
            if (r0 < Nn)
                *(float2*)(g_Wh + (size_t)r0 * 512 + cc) = make_float2(c[0], c[1]);
            if (r0 + 8 < Nn)
                *(float2*)(g_Wh + (size_t)(r0 + 8) * 512 + cc) = make_float2(c[2], c[3]);
        }
    }
}

// ---------------- HMMA GEMM2: g_Wh2[M,64] = h1 @ W_out ----------------------
#define A2_HI 0
#define A2_LO 10240
#define B2_HI 20480
#define B2_LO 25600
#define STAGE2 30720
#define SMEM_GEMM2_TOTAL (2 * STAGE2)

__device__ __forceinline__ void load_stage2(uint32_t s, int t, int m0, int kc) {
    int k0 = kc * 32;
#pragma unroll
    for (int i = 0; i < 2; i++) {
        int idx = t + i * 256;          // 0..511
        int r = idx >> 2;
        int c = idx & 3;
        uint32_t d = s + (uint32_t)(r * 80 + c * 16);
        size_t sa = (size_t)(m0 + r) * 512 + k0 + c * 8;
        cpa16(d + A2_HI, g_h1hi + sa);
        cpa16(d + A2_LO, g_h1lo + sa);
    }
    if (t < 256) {
        int r = t >> 2, c = t & 3;
        uint32_t d = s + (uint32_t)(r * 80 + c * 16);
        size_t sbg = (size_t)r * 512 + k0 + c * 8;
        cpa16(d + B2_HI, g_b2hi + sbg);
        cpa16(d + B2_LO, g_b2lo + sbg);
    }
    cpa_commit();
}

__global__ void __launch_bounds__(256) k_gemm2_mma() {
    extern __shared__ char smem[];
    uint32_t sb = smem_u32(smem);
    const int t = threadIdx.x;
    const int lane = t & 31, w = t >> 5;
    const int wm = w & 3, wn = w >> 2;          // 4(m) x 2(n), warp tile 32x32
    const int m0 = blockIdx.x * 128;

    float acc[2][4][4];
#pragma unroll
    for (int mf = 0; mf < 2; mf++)
#pragma unroll
        for (int nf = 0; nf < 4; nf++)
#pragma unroll
            for (int q = 0; q < 4; q++) acc[mf][nf][q] = 0.f;

    load_stage2(sb, t, m0, 0);

    const int a_row = wm * 32 + (lane & 15);
    const int a_colb = (lane >> 4) * 8;
    const int b_row = wn * 32 + ((lane >> 4) & 1) * 8 + (lane & 7);
    const int b_colb = ((lane >> 3) & 1) * 8;

    for (int kc = 0; kc < 16; kc++) {
        uint32_t s = sb + (uint32_t)(kc & 1) * STAGE2;
        if (kc + 1 < 16) load_stage2(sb + (uint32_t)((kc + 1) & 1) * STAGE2, t, m0, kc + 1);
        if (kc + 1 < 16) { cpa_wait<1>(); } else { cpa_wait<0>(); }
        __syncthreads();

#pragma unroll
        for (int ks = 0; ks < 2; ks++) {
            uint32_t ah[2][4], al[2][4];
#pragma unroll
            for (int mf = 0; mf < 2; mf++) {
                uint32_t ad = s + (uint32_t)((a_row + mf * 16) * 80 + (ks * 16 + a_colb) * 2);
                ldm4(ah[mf], ad + A2_HI);
                ldm4(al[mf], ad + A2_LO);
            }
            uint32_t bh[2][4], bl[2][4];
#pragma unroll
            for (int nb = 0; nb < 2; nb++) {
                uint32_t bd = s + (uint32_t)((b_row + nb * 16) * 80 + (ks * 16 + b_colb) * 2);
                ldm4(bh[nb], bd + B2_HI);
                ldm4(bl[nb], bd + B2_LO);
            }
#pragma unroll
            for (int mf = 0; mf < 2; mf++)
#pragma unroll
                for (int nb = 0; nb < 2; nb++)
#pragma unroll
                    for (int half = 0; half < 2; half++) {
                        float* c = acc[mf][nb * 2 + half];
                        mma16816(c, ah[mf], bh[nb][half * 2], bh[nb][half * 2 + 1]);
                        mma16816(c, ah[mf], bl[nb][half * 2], bl[nb][half * 2 + 1]);
                        mma16816(c, al[mf], bh[nb][half * 2], bh[nb][half * 2 + 1]);
                    }
        }
        __syncthreads();
    }

#pragma unroll
    for (int mf = 0; mf < 2; mf++) {
        int r0 = m0 + wm * 32 + mf * 16 + (lane >> 2);
#pragma unroll
        for (int nf = 0; nf < 4; nf++) {
            int cc = wn * 32 + nf * 8 + (lane & 3) * 2;
            float* c = acc[mf][nf];
            if (r0 < Nn)
                *(float2*)(g_Wh2 + (size_t)r0 * 64 + cc) = make_float2(c[0], c[1]);
            if (r0 + 8 < Nn)
                *(float2*)(g_Wh2 + (size_t)(r0 + 8) * 64 + cc) = make_float2(c[2], c[3]);
        }
    }
}

// ---------------- CSR build ------------------------------------------------
__global__ void k_zero_cnt() {
    int i = blockIdx.x * blockDim.x + threadIdx.x;
    if (i < Nn) g_cnt[i] = 0;
}

__global__ void k_hist(const int* __restrict__ row) {
    int e = blockIdx.x * blockDim.x + threadIdx.x;
    if (e < Ee) atomicAdd(&g_cnt[row[e]], 1);
}

__global__ void k_scan() {
    __shared__ int sh[2][1024];
    __shared__ int s_base;
    int t = threadIdx.x;
    if (t == 0) s_base = 0;
    __syncthreads();
    for (int start = 0; start < Nn; start += 1024) {
        int i = start + t;
        int v = (i < Nn) ? g_cnt[i] : 0;
        int orig = v;
        int pi = 0;
        sh[0][t] = v;
        __syncthreads();
        for (int s = 1; s < 1024; s <<= 1) {
            int w = sh[pi][t];
            if (t >= s) w += sh[pi][t - s];
            sh[pi ^ 1][t] = w;
            pi ^= 1;
            __syncthreads();
        }
        int incl = sh[pi][t];
        int base = s_base;
        if (i < Nn) {
            int ex = base + incl - orig;
            g_off[i] = ex;
            g_cur[i] = ex;
        }
        __syncthreads();
        if (t == 1023) s_base = base + incl;
        __syncthreads();
    }
    if (t == 0) g_off[Nn] = s_base;
}

__global__ void k_scatter(const int* __restrict__ row, const int* __restrict__ col) {
    int e = blockIdx.x * blockDim.x + threadIdx.x;
    if (e < Ee) {
        int r = row[e];
        int p = atomicAdd(&g_cur[r], 1);
        g_pos[e]  = p;
        g_rows[p] = r;
        g_cols[p] = col[e];
    }
}

// ---------------- layer1: f_dst/f_src per node ------------------------------
__global__ void k_f1(const float* __restrict__ a) {
    int i = blockIdx.x;
    int t = threadIdx.x;  // 256
    __shared__ float sd[512], ss[512];
    const float* whr = g_Wh + (size_t)i * 512;
    float v0 = whr[t], v1 = whr[t + 256];
    int h0 = t >> 6, j0 = t & 63;
    int idx1 = t + 256;
    int h1 = idx1 >> 6, j1 = idx1 & 63;
    sd[t]      = v0 * a[h0 * 128 + j0];
    ss[t]      = v0 * a[h0 * 128 + 64 + j0];
    sd[idx1]   = v1 * a[h1 * 128 + j1];
    ss[idx1]   = v1 * a[h1 * 128 + 64 + j1];
    __syncthreads();
    if (t < 16) {
        int h = t & 7;
        const float* buf = (t < 8) ? sd : ss;
        float s = 0.f;
#pragma unroll
        for (int j = 0; j < 64; j++) s += buf[h * 64 + j];
        if (t < 8) g_fd1[i * 8 + h] = s;
        else       g_fs1[i * 8 + h] = s;
    }
}

// ---------------- layer1: edge logits -> CSR slots --------------------------
__global__ void k_logits1(const int* __restrict__ row, const int* __restrict__ col) {
    int e = blockIdx.x * blockDim.x + threadIdx.x;
    if (e >= Ee) return;
    int r = row[e], c = col[e];
    float4 d0 = *(const float4*)(g_fd1 + r * 8);
    float4 d1 = *(const float4*)(g_fd1 + r * 8 + 4);
    float4 s0 = *(const float4*)(g_fs1 + c * 8);
    float4 s1 = *(const float4*)(g_fs1 + c * 8 + 4);
    float v[8] = {d0.x + s0.x, d0.y + s0.y, d0.z + s0.z, d0.w + s0.w,
                  d1.x + s1.x, d1.y + s1.y, d1.z + s1.z, d1.w + s1.w};
#pragma unroll
    for (int h = 0; h < 8; h++) v[h] = v[h] > 0.f ? v[h] : ALPHA * v[h];
    size_t p = (size_t)g_pos[e] * 8;
    *(float4*)(g_lg1 + p)     = make_float4(v[0], v[1], v[2], v[3]);
    *(float4*)(g_lg1 + p + 4) = make_float4(v[4], v[5], v[6], v[7]);
}

// ---------------- layer1: per (node,head) max + sumexp (warp/node) ----------
__global__ void k_maxsum1() {
    int gw = (blockIdx.x * blockDim.x + threadIdx.x) >> 5;  // node
    if (gw >= Nn) return;
    int lane = threadIdx.x & 31;
    int h = lane & 7, sub = lane >> 3;
    int o = g_off[gw], oe = g_off[gw + 1];
    float mx = -3.4e38f;
    for (int p = o + sub; p < oe; p += 4)
        mx = fmaxf(mx, g_lg1[(size_t)p * 8 + h]);
    mx = fmaxf(mx, __shfl_xor_sync(0xffffffffu, mx, 8));
    mx = fmaxf(mx, __shfl_xor_sync(0xffffffffu, mx, 16));
    float s = 0.f;
    for (int p = o + sub; p < oe; p += 4)
        s += __expf(g_lg1[(size_t)p * 8 + h] - mx);
    s += __shfl_xor_sync(0xffffffffu, s, 8);
    s += __shfl_xor_sync(0xffffffffu, s, 16);
    if (lane < 8) {
        float iv = (oe > o) ? 1.f / fmaxf(s, 1e-16f) : 0.f;
        g_mx1[gw * 8 + lane] = (oe > o) ? mx : 0.f;
        g_iv1[gw * 8 + lane] = iv;
    }
}

// ---------------- layer1: fused normalize + aggregation + ELU ----------------
__global__ void __launch_bounds__(256) k_agg1() {
    int i = blockIdx.x;
    int t = threadIdx.x;
    int o = g_off[i], oe = g_off[i + 1];
    __shared__ float s_mx[8], s_iv[8];
    __shared__ float s_att[32][8];
    __shared__ int   s_col[32];
    if (t < 8) { s_mx[t] = g_mx1[i * 8 + t]; s_iv[t] = g_iv1[i * 8 + t]; }
    int ha = t >> 6;
    int hb = ha + 4;
    float acc0 = 0.f, acc1 = 0.f;
    for (int base = o; base < oe; base += 32) {
        int cnt = min(32, oe - base);
        __syncthreads();
        {
            int j = t >> 3, h = t & 7;
            if (j < cnt)
                s_att[j][h] = __expf(g_lg1[(size_t)(base + j) * 8 + h] - s_mx[h]) * s_iv[h];
        }
        if (t < cnt) s_col[t] = g_cols[base + t];
        __syncthreads();
        for (int j = 0; j < cnt; j++) {
            int c = s_col[j];
            const float* whc = g_Wh + (size_t)c * 512;
            acc0 = fmaf(s_att[j][ha], whc[t], acc0);
            acc1 = fmaf(s_att[j][hb], whc[t + 256], acc1);
        }
    }
    float v0 = acc0 > 0.f ? acc0 : (__expf(acc0) - 1.f);
    float v1 = acc1 > 0.f ? acc1 : (__expf(acc1) - 1.f);
    size_t basew = (size_t)i * 512;
    __nv_bfloat16 h0 = __float2bfloat16_rn(v0);
    __nv_bfloat16 h1 = __float2bfloat16_rn(v1);
    g_h1hi[basew + t]       = h0;
    g_h1hi[basew + t + 256] = h1;
    g_h1lo[basew + t]       = __float2bfloat16_rn(v0 - __bfloat162float(h0));
    g_h1lo[basew + t + 256] = __float2bfloat16_rn(v1 - __bfloat162float(h1));
}

// ---------------- layer2 ------------------------------------------------------
__global__ void k_f2(const float* __restrict__ a_out) {
    int gt = blockIdx.x * blockDim.x + threadIdx.x;
    int w  = gt >> 5;
    int ln = gt & 31;
    if (w >= Nn) return;
    float v0 = g_Wh2[(size_t)w * 64 + ln];
    float v1 = g_Wh2[(size_t)w * 64 + 32 + ln];
    float pd = v0 * a_out[ln]      + v1 * a_out[ln + 32];
    float ps = v0 * a_out[64 + ln] + v1 * a_out[96 + ln];
#pragma unroll
    for (int s = 16; s > 0; s >>= 1) {
        pd += __shfl_down_sync(0xffffffffu, pd, s);
        ps += __shfl_down_sync(0xffffffffu, ps, s);
    }
    if (ln == 0) { g_fd2[w] = pd; g_fs2[w] = ps; }
}

__global__ void k_logits2(const int* __restrict__ row, const int* __restrict__ col) {
    int e = blockIdx.x * blockDim.x + threadIdx.x;
    if (e >= Ee) return;
    float v = g_fd2[row[e]] + g_fs2[col[e]];
    g_lg2[g_pos[e]] = v > 0.f ? v : ALPHA * v;
}

__global__ void k_maxsum2() {
    int gw = (blockIdx.x * blockDim.x + threadIdx.x) >> 5;
    if (gw >= Nn) return;
    int lane = threadIdx.x & 31;
    int o = g_off[gw], oe = g_off[gw + 1];
    float mx = -3.4e38f;
    for (int p = o + lane; p < oe; p += 32) mx = fmaxf(mx, g_lg2[p]);
#pragma unroll
    for (int s = 16; s > 0; s >>= 1) mx = fmaxf(mx, __shfl_xor_sync(0xffffffffu, mx, s));
    float sum = 0.f;
    for (int p = o + lane; p < oe; p += 32) sum += __expf(g_lg2[p] - mx);
#pragma unroll
    for (int s = 16; s > 0; s >>= 1) sum += __shfl_xor_sync(0xffffffffu, sum, s);
    if (lane == 0) {
        g_mx2[gw] = (oe > o) ? mx : 0.f;
        g_iv2[gw] = (oe > o) ? 1.f / fmaxf(sum, 1e-16f) : 0.f;
    }
}

// ---------------- layer2: fused normalize + aggregation ----------------------
__global__ void __launch_bounds__(64) k_agg2(float* __restrict__ out) {
    int i = blockIdx.x;
    int t = threadIdx.x;  // 64
    int o = g_off[i], oe = g_off[i + 1];
    __shared__ float s_att[64];
    __shared__ int   s_col[64];
    float mx = g_mx2[i], iv = g_iv2[i];
    float acc = 0.f;
    for (int base = o; base < oe; base += 64) {
        int cnt = min(64, oe - base);
        __syncthreads();
        if (t < cnt) {
            s_att[t] = __expf(g_lg2[base + t] - mx) * iv;
            s_col[t] = g_cols[base + t];
        }
        __syncthreads();
        for (int j = 0; j < cnt; j++)
            acc = fmaf(s_att[j], g_Wh2[(size_t)s_col[j] * 64 + t], acc);
    }
    out[(size_t)i * 64 + t] = acc;
}

// ---------------- launch -----------------------------------------------------
extern "C" void kernel_launch(void* const* d_in, const int* in_sizes, int n_in,
                              void* d_out, int out_size) {
    const float* x     = (const float*)d_in[0];
    const int*   row   = (const int*)  d_in[1];
    const int*   col   = (const int*)  d_in[2];
    const float* W     = (const float*)d_in[3];
    const float* a     = (const float*)d_in[4];
    const float* W_out = (const float*)d_in[5];
    const float* a_out = (const float*)d_in[6];
    float* out = (float*)d_out;

    const int EB = (Ee + 255) / 256;

    cudaFuncSetAttribute(k_gemm1_mma, cudaFuncAttributeMaxDynamicSharedMemorySize,
                         SMEM_GEMM_TOTAL);
    cudaFuncSetAttribute(k_gemm2_mma, cudaFuncAttributeMaxDynamicSharedMemorySize,
                         SMEM_GEMM2_TOTAL);

    // launches 0..4 (preamble so that launch #5 = k_gemm1_mma for ncu -s 5)
    k_cvt_x<<<(int)(((long long)Mpad * 128 + 255) / 256), 256>>>(x);      // 0
    k_cvt_w<<<(512 * 512 + 255) / 256, 256>>>(W);                          // 1
    k_cvt_w2<<<(64 * 512 + 255) / 256, 256>>>(W_out);                      // 2
    k_zero_cnt<<<(Nn + 255) / 256, 256>>>();                               // 3
    k_hist<<<EB, 256>>>(row);                                              // 4

    // launch 5: the big GEMM (profiled by ncu -s 5 -c 1)
    k_gemm1_mma<<<dim3(Mpad / 128, 4), 256, SMEM_GEMM_TOTAL>>>();          // 5

    // rest of CSR build
    k_scan<<<1, 1024>>>();                                                 // 6
    k_scatter<<<EB, 256>>>(row, col);                                      // 7

    // layer 1
    k_f1<<<Nn, 256>>>(a);                                                  // 8
    k_logits1<<<EB, 256>>>(row, col);                                      // 9
    k_maxsum1<<<(Nn * 32 + 255) / 256, 256>>>();                           // 10
    k_agg1<<<Nn, 256>>>();                                                 // 11

    // layer 2
    k_gemm2_mma<<<Mpad / 128, 256, SMEM_GEMM2_TOTAL>>>();                  // 12
    k_f2<<<(Nn * 32 + 255) / 256, 256>>>(a_out);                           // 13
    k_logits2<<<EB, 256>>>(row, col);                                      // 14
    k_maxsum2<<<(Nn * 32 + 255) / 256, 256>>>();                           // 15
    k_agg2<<<Nn, 64>>>(out);                                               // 16
}

// round 7
// speedup vs baseline: 1.7922x; 1.0603x over previous
#include <cuda_runtime.h>
#include <cuda_bf16.h>
#include <stdint.h>
#include <math.h>

// Problem constants
#define Nn    50000
#define Mpad  50048
#define Ee    800000
#define FEAT  512
#define HEADS 8
#define HID   64
#define C1    512
#define NC    64
#define ALPHA 0.2f

// ---------------- scratch -----------------------------------------------------
__device__ float g_Wh [(size_t)Nn * C1];
__device__ float g_Wh2[(size_t)Nn * NC];
__device__ float g_fd1[Nn * HEADS];
__device__ float g_fs1[Nn * HEADS];
__device__ float g_fd2[Nn];
__device__ float g_fs2[Nn];
__device__ float g_lg1[(size_t)Ee * HEADS]; // CSR-ordered raw logits
__device__ float g_lg2[Ee];                 // CSR-ordered raw logits
__device__ int   g_cnt[Nn];
__device__ int   g_off[Nn + 1];
__device__ int   g_cur[Nn];
__device__ int   g_pos [Ee];   // edge e -> CSR slot p
__device__ int   g_cols[Ee];   // CSR slot p -> src node

// bf16 hi/lo operands
__device__ __align__(256) __nv_bfloat16 g_xhi[(size_t)Mpad * 512];
__device__ __align__(256) __nv_bfloat16 g_xlo[(size_t)Mpad * 512];
__device__ __align__(256) __nv_bfloat16 g_bhi[512 * 512];
__device__ __align__(256) __nv_bfloat16 g_blo[512 * 512];
__device__ __align__(256) __nv_bfloat16 g_h1hi[(size_t)Mpad * 512];  // pad rows stay 0
__device__ __align__(256) __nv_bfloat16 g_h1lo[(size_t)Mpad * 512];
__device__ __align__(256) __nv_bfloat16 g_b2hi[64 * 512];
__device__ __align__(256) __nv_bfloat16 g_b2lo[64 * 512];

// ---------------- PTX helpers --------------------------------------------------
__device__ __forceinline__ uint32_t smem_u32(const void* p) {
    uint32_t a;
    asm("{ .reg .u64 t; cvta.to.shared.u64 t, %1; cvt.u32.u64 %0, t; }" : "=r"(a) : "l"(p));
    return a;
}
__device__ __forceinline__ void cpa16(uint32_t dst, const void* src) {
    asm volatile("cp.async.cg.shared.global [%0], [%1], 16;" :: "r"(dst), "l"(src));
}
__device__ __forceinline__ void cpa_commit() {
    asm volatile("cp.async.commit_group;" ::: "memory");
}
template <int N> __device__ __forceinline__ void cpa_wait() {
    asm volatile("cp.async.wait_group %0;" :: "n"(N) : "memory");
}
__device__ __forceinline__ void ldm4(uint32_t* r, uint32_t addr) {
    asm volatile("ldmatrix.sync.aligned.m8n8.x4.shared.b16 {%0,%1,%2,%3}, [%4];"
                 : "=r"(r[0]), "=r"(r[1]), "=r"(r[2]), "=r"(r[3]) : "r"(addr));
}
__device__ __forceinline__ void mma16816(float* c, const uint32_t* a,
                                         uint32_t b0, uint32_t b1) {
    asm volatile(
        "mma.sync.aligned.m16n8k16.row.col.f32.bf16.bf16.f32 "
        "{%0,%1,%2,%3}, {%4,%5,%6,%7}, {%8,%9}, {%0,%1,%2,%3};"
        : "+f"(c[0]), "+f"(c[1]), "+f"(c[2]), "+f"(c[3])
        : "r"(a[0]), "r"(a[1]), "r"(a[2]), "r"(a[3]), "r"(b0), "r"(b1));
}

// ---------------- conversion kernels --------------------------------------------
__global__ void k_cvt_x(const float* __restrict__ x) {
    long long i4 = (long long)blockIdx.x * blockDim.x + threadIdx.x;
    if (i4 >= (long long)Mpad * 128) return;
    long long row = i4 >> 7;
    float4 v = make_float4(0.f, 0.f, 0.f, 0.f);
    if (row < Nn) v = ((const float4*)x)[i4];
    __nv_bfloat16 h0 = __float2bfloat16_rn(v.x);
    __nv_bfloat16 h1 = __float2bfloat16_rn(v.y);
    __nv_bfloat16 h2 = __float2bfloat16_rn(v.z);
    __nv_bfloat16 h3 = __float2bfloat16_rn(v.w);
    __nv_bfloat16 l0 = __float2bfloat16_rn(v.x - __bfloat162float(h0));
    __nv_bfloat16 l1 = __float2bfloat16_rn(v.y - __bfloat162float(h1));
    __nv_bfloat16 l2 = __float2bfloat16_rn(v.z - __bfloat162float(h2));
    __nv_bfloat16 l3 = __float2bfloat16_rn(v.w - __bfloat162float(h3));
    __nv_bfloat16* ph = g_xhi + i4 * 4;
    __nv_bfloat16* pl = g_xlo + i4 * 4;
    ph[0] = h0; ph[1] = h1; ph[2] = h2; ph[3] = h3;
    pl[0] = l0; pl[1] = l1; pl[2] = l2; pl[3] = l3;
}

__global__ void k_cvt_w(const float* __restrict__ W) {
    int idx = blockIdx.x * blockDim.x + threadIdx.x;
    if (idx >= 512 * 512) return;
    int n = idx >> 9, k = idx & 511;
    float v = W[(size_t)(n >> 6) * (512 * 64) + (size_t)k * 64 + (n & 63)];
    __nv_bfloat16 h = __float2bfloat16_rn(v);
    __nv_bfloat16 l = __float2bfloat16_rn(v - __bfloat162float(h));
    g_bhi[idx] = h;
    g_blo[idx] = l;
}

__global__ void k_cvt_w2(const float* __restrict__ W_out) {
    int idx = blockIdx.x * blockDim.x + threadIdx.x;
    if (idx >= 64 * 512) return;
    int n = idx >> 9, k = idx & 511;
    float v = W_out[(size_t)k * 64 + n];
    __nv_bfloat16 h = __float2bfloat16_rn(v);
    __nv_bfloat16 l = __float2bfloat16_rn(v - __bfloat162float(h));
    g_b2hi[idx] = h;
    g_b2lo[idx] = l;
}

// ---------------- HMMA GEMM1 (+f1 epilogue) -----------------------------------
#define A_HI 0
#define A_LO 10240
#define B_HI 20480
#define B_LO 30720
#define STAGE 40960
#define SMEM_GEMM_TOTAL (2 * STAGE)

__device__ __forceinline__ void load_stage(uint32_t s, int t, int m0, int n0, int kc) {
    int k0 = kc * 32;
#pragma unroll
    for (int i = 0; i < 2; i++) {
        int idx = t + i * 256;
        int r = idx >> 2;
        int c = idx & 3;
        uint32_t d = s + (uint32_t)(r * 80 + c * 16);
        size_t sa = (size_t)(m0 + r) * 512 + k0 + c * 8;
        size_t sbg = (size_t)(n0 + r) * 512 + k0 + c * 8;
        cpa16(d + A_HI, g_xhi + sa);
        cpa16(d + A_LO, g_xlo + sa);
        cpa16(d + B_HI, g_bhi + sbg);
        cpa16(d + B_LO, g_blo + sbg);
    }
    cpa_commit();
}

__global__ void __launch_bounds__(256) k_gemm1_mma(const float* __restrict__ a_vec) {
    extern __shared__ char smem[];
    __shared__ float s_ad[2][64], s_as[2][64];
    uint32_t sb = smem_u32(smem);
    const int t = threadIdx.x;
    const int lane = t & 31, w = t >> 5;
    const int wm = w & 3, wn = w >> 2;
    const int m0 = blockIdx.x * 128, n0 = blockIdx.y * 128;

    if (t < 128) {
        int hh = t >> 6, j = t & 63;
        int gh = blockIdx.y * 2 + hh;
        s_ad[hh][j] = a_vec[gh * 128 + j];
        s_as[hh][j] = a_vec[gh * 128 + 64 + j];
    }

    float acc[2][8][4];
#pragma unroll
    for (int mf = 0; mf < 2; mf++)
#pragma unroll
        for (int nf = 0; nf < 8; nf++)
#pragma unroll
            for (int q = 0; q < 4; q++) acc[mf][nf][q] = 0.f;

    load_stage(sb, t, m0, n0, 0);

    const int a_row = wm * 32 + (lane & 15);
    const int a_colb = (lane >> 4) * 8;
    const int b_row = wn * 64 + ((lane >> 4) & 1) * 8 + (lane & 7);
    const int b_colb = ((lane >> 3) & 1) * 8;

    for (int kc = 0; kc < 16; kc++) {
        uint32_t s = sb + (uint32_t)(kc & 1) * STAGE;
        if (kc + 1 < 16) load_stage(sb + (uint32_t)((kc + 1) & 1) * STAGE, t, m0, n0, kc + 1);
        if (kc + 1 < 16) { cpa_wait<1>(); } else { cpa_wait<0>(); }
        __syncthreads();

#pragma unroll
        for (int ks = 0; ks < 2; ks++) {
            uint32_t ah[2][4], al[2][4];
#pragma unroll
            for (int mf = 0; mf < 2; mf++) {
                uint32_t ad = s + (uint32_t)((a_row + mf * 16) * 80 + (ks * 16 + a_colb) * 2);
                ldm4(ah[mf], ad + A_HI);
                ldm4(al[mf], ad + A_LO);
            }
            uint32_t bh[4][4], bl[4][4];
#pragma unroll
            for (int nb = 0; nb < 4; nb++) {
                uint32_t bd = s + (uint32_t)((b_row + nb * 16) * 80 + (ks * 16 + b_colb) * 2);
                ldm4(bh[nb], bd + B_HI);
                ldm4(bl[nb], bd + B_LO);
            }
#pragma unroll
            for (int mf = 0; mf < 2; mf++)
#pragma unroll
                for (int nb = 0; nb < 4; nb++)
#pragma unroll
                    for (int half = 0; half < 2; half++) {
                        float* c = acc[mf][nb * 2 + half];
                        mma16816(c, ah[mf], bh[nb][half * 2], bh[nb][half * 2 + 1]);
                        mma16816(c, ah[mf], bl[nb][half * 2], bl[nb][half * 2 + 1]);
                        mma16816(c, al[mf], bh[nb][half * 2], bh[nb][half * 2 + 1]);
                    }
        }
        __syncthreads();
    }

    // epilogue: store Wh + fused f1 (per-row dot with a head vectors)
    const int ghead = blockIdx.y * 2 + wn;
#pragma unroll
    for (int mf = 0; mf < 2; mf++) {
        int rbase = m0 + wm * 32 + mf * 16 + (lane >> 2);
#pragma unroll
        for (int nf = 0; nf < 8; nf++) {
            int cc = n0 + wn * 64 + nf * 8 + (lane & 3) * 2;
            float* c = acc[mf][nf];
            if (rbase < Nn)
                *(float2*)(g_Wh + (size_t)rbase * 512 + cc) = make_float2(c[0], c[1]);
            if (rbase + 8 < Nn)
                *(float2*)(g_Wh + (size_t)(rbase + 8) * 512 + cc) = make_float2(c[2], c[3]);
        }
#pragma unroll
        for (int half = 0; half < 2; half++) {
            float pd = 0.f, ps = 0.f;
#pragma unroll
            for (int nf = 0; nf < 8; nf++) {
                int j0 = nf * 8 + (lane & 3) * 2;
                float c0 = acc[mf][nf][half * 2 + 0];
                float c1 = acc[mf][nf][half * 2 + 1];
                pd += c0 * s_ad[wn][j0] + c1 * s_ad[wn][j0 + 1];
                ps += c0 * s_as[wn][j0] + c1 * s_as[wn][j0 + 1];
            }
            pd += __shfl_xor_sync(0xffffffffu, pd, 1);
            pd += __shfl_xor_sync(0xffffffffu, pd, 2);
            ps += __shfl_xor_sync(0xffffffffu, ps, 1);
            ps += __shfl_xor_sync(0xffffffffu, ps, 2);
            int r = rbase + half * 8;
            if ((lane & 3) == 0 && r < Nn) {
                g_fd1[r * 8 + ghead] = pd;
                g_fs1[r * 8 + ghead] = ps;
            }
        }
    }
}

// ---------------- HMMA GEMM2 (+f2 epilogue) -----------------------------------
#define A2_HI 0
#define A2_LO 10240
#define B2_HI 20480
#define B2_LO 25600
#define STAGE2 30720
#define SMEM_GEMM2_TOTAL (2 * STAGE2)

__device__ __forceinline__ void load_stage2(uint32_t s, int t, int m0, int kc) {
    int k0 = kc * 32;
#pragma unroll
    for (int i = 0; i < 2; i++) {
        int idx = t + i * 256;
        int r = idx >> 2;
        int c = idx & 3;
        uint32_t d = s + (uint32_t)(r * 80 + c * 16);
        size_t sa = (size_t)(m0 + r) * 512 + k0 + c * 8;
        cpa16(d + A2_HI, g_h1hi + sa);
        cpa16(d + A2_LO, g_h1lo + sa);
    }
    if (t < 256) {
        int r = t >> 2, c = t & 3;
        uint32_t d = s + (uint32_t)(r * 80 + c * 16);
        size_t sbg = (size_t)r * 512 + k0 + c * 8;
        cpa16(d + B2_HI, g_b2hi + sbg);
        cpa16(d + B2_LO, g_b2lo + sbg);
    }
    cpa_commit();
}

__global__ void __launch_bounds__(256) k_gemm2_mma(const float* __restrict__ a_out) {
    extern __shared__ char smem[];
    __shared__ float s_a2d[64], s_a2s[64];
    __shared__ float s_pd[2][128], s_ps[2][128];
    uint32_t sb = smem_u32(smem);
    const int t = threadIdx.x;
    const int lane = t & 31, w = t >> 5;
    const int wm = w & 3, wn = w >> 2;
    const int m0 = blockIdx.x * 128;

    if (t < 64) {
        s_a2d[t] = a_out[t];
        s_a2s[t] = a_out[64 + t];
    }

    float acc[2][4][4];
#pragma unroll
    for (int mf = 0; mf < 2; mf++)
#pragma unroll
        for (int nf = 0; nf < 4; nf++)
#pragma unroll
            for (int q = 0; q < 4; q++) acc[mf][nf][q] = 0.f;

    load_stage2(sb, t, m0, 0);

    const int a_row = wm * 32 + (lane & 15);
    const int a_colb = (lane >> 4) * 8;
    const int b_row = wn * 32 + ((lane >> 4) & 1) * 8 + (lane & 7);
    const int b_colb = ((lane >> 3) & 1) * 8;

    for (int kc = 0; kc < 16; kc++) {
        uint32_t s = sb + (uint32_t)(kc & 1) * STAGE2;
        if (kc + 1 < 16) load_stage2(sb + (uint32_t)((kc + 1) & 1) * STAGE2, t, m0, kc + 1);
        if (kc + 1 < 16) { cpa_wait<1>(); } else { cpa_wait<0>(); }
        __syncthreads();

#pragma unroll
        for (int ks = 0; ks < 2; ks++) {
            uint32_t ah[2][4], al[2][4];
#pragma unroll
            for (int mf = 0; mf < 2; mf++) {
                uint32_t ad = s + (uint32_t)((a_row + mf * 16) * 80 + (ks * 16 + a_colb) * 2);
                ldm4(ah[mf], ad + A2_HI);
                ldm4(al[mf], ad + A2_LO);
            }
            uint32_t bh[2][4], bl[2][4];
#pragma unroll
            for (int nb = 0; nb < 2; nb++) {
                uint32_t bd = s + (uint32_t)((b_row + nb * 16) * 80 + (ks * 16 + b_colb) * 2);
                ldm4(bh[nb], bd + B2_HI);
                ldm4(bl[nb], bd + B2_LO);
            }
#pragma unroll
            for (int mf = 0; mf < 2; mf++)
#pragma unroll
                for (int nb = 0; nb < 2; nb++)
#pragma unroll
                    for (int half = 0; half < 2; half++) {
                        float* c = acc[mf][nb * 2 + half];
                        mma16816(c, ah[mf], bh[nb][half * 2], bh[nb][half * 2 + 1]);
                        mma16816(c, ah[mf], bl[nb][half * 2], bl[nb][half * 2 + 1]);
                        mma16816(c, al[mf], bh[nb][half * 2], bh[nb][half * 2 + 1]);
                    }
        }
        __syncthreads();
    }

    // epilogue: store Wh2 + per-warp partial f2 dots
#pragma unroll
    for (int mf = 0; mf < 2; mf++) {
        int rbase = m0 + wm * 32 + mf * 16 + (lane >> 2);
#pragma unroll
        for (int nf = 0; nf < 4; nf++) {
            int cc = wn * 32 + nf * 8 + (lane & 3) * 2;
            float* c = acc[mf][nf];
            if (rbase < Nn)
                *(float2*)(g_Wh2 + (size_t)rbase * 64 + cc) = make_float2(c[0], c[1]);
            if (rbase + 8 < Nn)
                *(float2*)(g_Wh2 + (size_t)(rbase + 8) * 64 + cc) = make_float2(c[2], c[3]);
        }
#pragma unroll
        for (int half = 0; half < 2; half++) {
            float pd = 0.f, ps = 0.f;
#pragma unroll
            for (int nf = 0; nf < 4; nf++) {
                int j0 = wn * 32 + nf * 8 + (lane & 3) * 2;
                float c0 = acc[mf][nf][half * 2 + 0];
                float c1 = acc[mf][nf][half * 2 + 1];
                pd += c0 * s_a2d[j0] + c1 * s_a2d[j0 + 1];
                ps += c0 * s_a2s[j0] + c1 * s_a2s[j0 + 1];
            }
            pd += __shfl_xor_sync(0xffffffffu, pd, 1);
            pd += __shfl_xor_sync(0xffffffffu, pd, 2);
            ps += __shfl_xor_sync(0xffffffffu, ps, 1);
            ps += __shfl_xor_sync(0xffffffffu, ps, 2);
            int rl = wm * 32 + mf * 16 + (lane >> 2) + half * 8;
            if ((lane & 3) == 0) {
                s_pd[wn][rl] = pd;
                s_ps[wn][rl] = ps;
            }
        }
    }
    __syncthreads();
    if (t < 128) {
        int r = m0 + t;
        if (r < Nn) {
            g_fd2[r] = s_pd[0][t] + s_pd[1][t];
            g_fs2[r] = s_ps[0][t] + s_ps[1][t];
        }
    }
}

// ---------------- CSR build ------------------------------------------------
__global__ void k_zero_cnt() {
    int i = blockIdx.x * blockDim.x + threadIdx.x;
    if (i < Nn) g_cnt[i] = 0;
}

__global__ void k_hist(const int* __restrict__ row) {
    int e = blockIdx.x * blockDim.x + threadIdx.x;
    if (e < Ee) atomicAdd(&g_cnt[row[e]], 1);
}

__global__ void k_scan() {   // 1024 threads, shfl-based
    __shared__ int s_w[32];
    __shared__ int s_base, s_next;
    int t = threadIdx.x, lane = t & 31, wid = t >> 5;
    if (t == 0) s_base = 0;
    __syncthreads();
    for (int start = 0; start < Nn; start += 1024) {
        int i = start + t;
        int v = (i < Nn) ? g_cnt[i] : 0;
        int sc = v;
#pragma unroll
        for (int d = 1; d < 32; d <<= 1) {
            int u = __shfl_up_sync(0xffffffffu, sc, d);
            if (lane >= d) sc += u;
        }
        if (lane == 31) s_w[wid] = sc;
        __syncthreads();
        if (wid == 0) {
            int wsc = s_w[lane];
#pragma unroll
            for (int d = 1; d < 32; d <<= 1) {
                int u = __shfl_up_sync(0xffffffffu, wsc, d);
                if (lane >= d) wsc += u;
            }
            s_w[lane] = wsc;
            if (lane == 31) s_next = wsc;
        }
        __syncthreads();
        int base = s_base;
        int warpoff = (wid == 0) ? 0 : s_w[wid - 1];
        int ex = base + warpoff + sc - v;
        if (i < Nn) { g_off[i] = ex; g_cur[i] = ex; }
        __syncthreads();
        if (t == 0) s_base = base + s_next;
        __syncthreads();
    }
    if (t == 0) g_off[Nn] = s_base;
}

__global__ void k_scatter(const int* __restrict__ row, const int* __restrict__ col) {
    int e = blockIdx.x * blockDim.x + threadIdx.x;
    if (e < Ee) {
        int r = row[e];
        int p = atomicAdd(&g_cur[r], 1);
        g_pos[e]  = p;
        g_cols[p] = col[e];
    }
}

// ---------------- layer1: edge logits -> CSR slots --------------------------
__global__ void k_logits1(const int* __restrict__ row, const int* __restrict__ col) {
    int e = blockIdx.x * blockDim.x + threadIdx.x;
    if (e >= Ee) return;
    int r = row[e], c = col[e];
    float4 d0 = *(const float4*)(g_fd1 + r * 8);
    float4 d1 = *(const float4*)(g_fd1 + r * 8 + 4);
    float4 s0 = *(const float4*)(g_fs1 + c * 8);
    float4 s1 = *(const float4*)(g_fs1 + c * 8 + 4);
    float v[8] = {d0.x + s0.x, d0.y + s0.y, d0.z + s0.z, d0.w + s0.w,
                  d1.x + s1.x, d1.y + s1.y, d1.z + s1.z, d1.w + s1.w};
#pragma unroll
    for (int h = 0; h < 8; h++) v[h] = v[h] > 0.f ? v[h] : ALPHA * v[h];
    size_t p = (size_t)g_pos[e] * 8;
    *(float4*)(g_lg1 + p)     = make_float4(v[0], v[1], v[2], v[3]);
    *(float4*)(g_lg1 + p + 4) = make_float4(v[4], v[5], v[6], v[7]);
}

// ---------------- layer1: fused softmax stats + aggregation + ELU ------------
__global__ void __launch_bounds__(256) k_agg1() {
    int i = blockIdx.x;
    int t = threadIdx.x;
    int o = g_off[i], oe = g_off[i + 1];
    __shared__ float s_red[32][8];
    __shared__ float s_mx[8], s_iv[8];
    __shared__ float s_att[32][8];
    __shared__ int   s_col[32];
    int j = t >> 3, h = t & 7;

    // pass 1: max per head
    float mx = -3.4e38f;
    for (int p = o + j; p < oe; p += 32)
        mx = fmaxf(mx, g_lg1[(size_t)p * 8 + h]);
    s_red[j][h] = mx;
    __syncthreads();
#pragma unroll
    for (int s = 16; s > 0; s >>= 1) {
        if (j < s) s_red[j][h] = fmaxf(s_red[j][h], s_red[j + s][h]);
        __syncthreads();
    }
    float mxh = s_red[0][h];
    __syncthreads();
    // pass 2: sum of exp
    float sm = 0.f;
    for (int p = o + j; p < oe; p += 32)
        sm += __expf(g_lg1[(size_t)p * 8 + h] - mxh);
    s_red[j][h] = sm;
    __syncthreads();
#pragma unroll
    for (int s = 16; s > 0; s >>= 1) {
        if (j < s) s_red[j][h] += s_red[j + s][h];
        __syncthreads();
    }
    if (t < 8) {
        s_mx[t] = (oe > o) ? s_red[0][t] * 0.f + mxh * 0.f + s_mx[t] * 0.f : 0.f; // placeholder, overwritten below
    }
    // (write stats: one thread per head)
    if (j == 0) {
        s_mx[h] = (oe > o) ? mxh : 0.f;
        s_iv[h] = (oe > o) ? 1.f / fmaxf(s_red[0][h], 1e-16f) : 0.f;
    }
    __syncthreads();

    int ha = t >> 6;
    int hb = ha + 4;
    float acc0 = 0.f, acc1 = 0.f;
    for (int base = o; base < oe; base += 32) {
        int cnt = min(32, oe - base);
        __syncthreads();
        if (j < cnt)
            s_att[j][h] = __expf(g_lg1[(size_t)(base + j) * 8 + h] - s_mx[h]) * s_iv[h];
        if (t < cnt) s_col[t] = g_cols[base + t];
        __syncthreads();
        for (int q = 0; q < cnt; q++) {
            int c = s_col[q];
            const float* whc = g_Wh + (size_t)c * 512;
            acc0 = fmaf(s_att[q][ha], whc[t], acc0);
            acc1 = fmaf(s_att[q][hb], whc[t + 256], acc1);
        }
    }
    float v0 = acc0 > 0.f ? acc0 : (__expf(acc0) - 1.f);
    float v1 = acc1 > 0.f ? acc1 : (__expf(acc1) - 1.f);
    size_t basew = (size_t)i * 512;
    __nv_bfloat16 h0 = __float2bfloat16_rn(v0);
    __nv_bfloat16 h1 = __float2bfloat16_rn(v1);
    g_h1hi[basew + t]       = h0;
    g_h1hi[basew + t + 256] = h1;
    g_h1lo[basew + t]       = __float2bfloat16_rn(v0 - __bfloat162float(h0));
    g_h1lo[basew + t + 256] = __float2bfloat16_rn(v1 - __bfloat162float(h1));
}

// ---------------- layer2: edge logits ---------------------------------------
__global__ void k_logits2(const int* __restrict__ row, const int* __restrict__ col) {
    int e = blockIdx.x * blockDim.x + threadIdx.x;
    if (e >= Ee) return;
    float v = g_fd2[row[e]] + g_fs2[col[e]];
    g_lg2[g_pos[e]] = v > 0.f ? v : ALPHA * v;
}

// ---------------- layer2: fused stats + aggregation --------------------------
__global__ void __launch_bounds__(64) k_agg2(float* __restrict__ out) {
    int i = blockIdx.x;
    int t = threadIdx.x;  // 64
    int o = g_off[i], oe = g_off[i + 1];
    __shared__ float s_r[64];
    __shared__ float s_att[64];
    __shared__ int   s_col[64];

    float mx = -3.4e38f;
    for (int p = o + t; p < oe; p += 64) mx = fmaxf(mx, g_lg2[p]);
    s_r[t] = mx;
    __syncthreads();
#pragma unroll
    for (int s = 32; s > 0; s >>= 1) {
        if (t < s) s_r[t] = fmaxf(s_r[t], s_r[t + s]);
        __syncthreads();
    }
    float M = s_r[0];
    __syncthreads();
    float sm = 0.f;
    for (int p = o + t; p < oe; p += 64) sm += __expf(g_lg2[p] - M);
    s_r[t] = sm;
    __syncthreads();
#pragma unroll
    for (int s = 32; s > 0; s >>= 1) {
        if (t < s) s_r[t] += s_r[t + s];
        __syncthreads();
    }
    float iv = (oe > o) ? 1.f / fmaxf(s_r[0], 1e-16f) : 0.f;
    __syncthreads();

    float acc = 0.f;
    for (int base = o; base < oe; base += 64) {
        int cnt = min(64, oe - base);
        __syncthreads();
        if (t < cnt) {
            s_att[t] = __expf(g_lg2[base + t] - M) * iv;
            s_col[t] = g_cols[base + t];
        }
        __syncthreads();
        for (int q = 0; q < cnt; q++)
            acc = fmaf(s_att[q], g_Wh2[(size_t)s_col[q] * 64 + t], acc);
    }
    out[(size_t)i * 64 + t] = acc;
}

// ---------------- launch -----------------------------------------------------
extern "C" void kernel_launch(void* const* d_in, const int* in_sizes, int n_in,
                              void* d_out, int out_size) {
    const float* x     = (const float*)d_in[0];
    const int*   row   = (const int*)  d_in[1];
    const int*   col   = (const int*)  d_in[2];
    const float* W     = (const float*)d_in[3];
    const float* a     = (const float*)d_in[4];
    const float* W_out = (const float*)d_in[5];
    const float* a_out = (const float*)d_in[6];
    float* out = (float*)d_out;

    const int EB = (Ee + 255) / 256;

    cudaFuncSetAttribute(k_gemm1_mma, cudaFuncAttributeMaxDynamicSharedMemorySize,
                         SMEM_GEMM_TOTAL);
    cudaFuncSetAttribute(k_gemm2_mma, cudaFuncAttributeMaxDynamicSharedMemorySize,
                         SMEM_GEMM2_TOTAL);

    k_cvt_x<<<(int)(((long long)Mpad * 128 + 255) / 256), 256>>>(x);
    k_cvt_w<<<(512 * 512 + 255) / 256, 256>>>(W);
    k_cvt_w2<<<(64 * 512 + 255) / 256, 256>>>(W_out);
    k_zero_cnt<<<(Nn + 255) / 256, 256>>>();
    k_hist<<<EB, 256>>>(row);

    k_gemm1_mma<<<dim3(Mpad / 128, 4), 256, SMEM_GEMM_TOTAL>>>(a);

    k_scan<<<1, 1024>>>();
    k_scatter<<<EB, 256>>>(row, col);

    k_logits1<<<EB, 256>>>(row, col);
    k_agg1<<<Nn, 256>>>();

    k_gemm2_mma<<<Mpad / 128, 256, SMEM_GEMM2_TOTAL>>>(a_out);
    k_logits2<<<EB, 256>>>(row, col);
    k_agg2<<<Nn, 64>>>(out);
}